// round 2
// baseline (speedup 1.0000x reference)
#include <cuda_runtime.h>
#include <math.h>

// ---------------------------------------------------------------------------
// BlindSpotBlock: shifted-window blind-spot attention + proj + MLP
// B=8 H=256 W=256 C=96, WS=8 SS=4 NH=6 CH=16, NP=64, NW=1024, B*NW=8192
// f32x2-packed SIMT implementation.
// ---------------------------------------------------------------------------

#define NPIX   (8*256*256)
#define CDIM   96

__device__ float g_X[NPIX * CDIM];      // attention-half output (B,H,W,C)

typedef unsigned long long u64;

__device__ __forceinline__ u64 pack2(float lo, float hi){
    u64 r; asm("mov.b64 %0, {%1, %2};" : "=l"(r) : "f"(lo), "f"(hi)); return r;
}
__device__ __forceinline__ u64 packdup(float x){
    u64 r; asm("mov.b64 %0, {%1, %1};" : "=l"(r) : "f"(x)); return r;
}
__device__ __forceinline__ void unpack2(u64 v, float& lo, float& hi){
    asm("mov.b64 {%0, %1}, %2;" : "=f"(lo), "=f"(hi) : "l"(v));
}
__device__ __forceinline__ u64 ffma2(u64 a, u64 b, u64 c){
    u64 d; asm("fma.rn.f32x2 %0, %1, %2, %3;" : "=l"(d) : "l"(a), "l"(b), "l"(c)); return d;
}
__device__ __forceinline__ u64 fmul2(u64 a, u64 b){
    u64 d; asm("mul.rn.f32x2 %0, %1, %2;" : "=l"(d) : "l"(a), "l"(b)); return d;
}

// ---- Kernel A ------------------------------------------------------------
// smem (floats):
//   k_s   [0,     6144)   64x96
//   v_s   [6144, 12288)   64x96
//   w_s   [0,     9408)   96x98 (c_out-major, pad 98) -- reused post-attention
//   out_t [12288,18432)   96x64 transposed activation [c][row]
//   rpb_s [18432,19782)   225x6
//   base_s[19782,19846)   int
//   reg_s [19846,19910)   int
#define A_SMEM_FLOATS 19910

__global__ void __launch_bounds__(384, 2)
attn_proj_kernel(const float* __restrict__ q_in,
                 const float* __restrict__ k_in,
                 const float* __restrict__ v_in,
                 const float* __restrict__ rpb,
                 const float* __restrict__ ng,
                 const float* __restrict__ nb,
                 const float* __restrict__ pw,
                 const float* __restrict__ pb)
{
    extern __shared__ float sm[];
    float* k_s    = sm;
    float* v_s    = sm + 6144;
    float* w_s    = sm;
    float* out_t  = sm + 12288;          // [c][row], stride 64
    float* rpb_s  = sm + 18432;
    int*   base_s = (int*)(sm + 19782);
    int*   reg_s  = (int*)(sm + 19846);

    const int tid  = threadIdx.x;
    const int w    = blockIdx.x;
    const int b    = w >> 10;
    const int widx = w & 1023;
    const int wy   = widx >> 5;
    const int wx   = widx & 31;

    if (tid < 64) {
        const int py = tid >> 3, px = tid & 7;
        const int ys = (wy * 8 + py + 4) & 255;
        const int xs = (wx * 8 + px + 4) & 255;
        base_s[tid] = ((b * 256 + ys) * 256 + xs) * 96;
        const int row = wy * 8 + py, col = wx * 8 + px;
        const int rr = (row < 248) ? 0 : ((row < 252) ? 1 : 2);
        const int cr = (col < 248) ? 0 : ((col < 252) ? 1 : 2);
        reg_s[tid] = rr * 3 + cr;
    }
    for (int n = tid; n < 1350; n += 384) rpb_s[n] = rpb[n];
    __syncthreads();

    // gather K/V tiles, float4
    for (int n = tid; n < 1536; n += 384) {
        const int p = n / 24, c4 = n % 24;
        const int g = base_s[p] + c4 * 4;
        *(float4*)(k_s + p * 96 + c4 * 4) = *(const float4*)(k_in + g);
        *(float4*)(v_s + p * 96 + c4 * 4) = *(const float4*)(v_in + g);
    }
    __syncthreads();

    // thread = (head hh, query row i)
    const int hh = tid >> 6;
    const int i  = tid & 63;
    const int co = hh * 16;
    const int yi = i >> 3, xi = i & 7;
    const int ri = reg_s[i];
    const int myoff = (112 + yi * 15 + xi) * 6 + hh;   // bias base index

    // q (scaled) packed: 8 pairs
    u64 q2[8];
    {
        const ulonglong2* qp = (const ulonglong2*)(q_in + base_s[i] + co);
        const u64 s2 = packdup(0.25f);
        ulonglong2 a = qp[0], bq = qp[1], c = qp[2], d = qp[3];
        q2[0] = fmul2(a.x, s2);  q2[1] = fmul2(a.y, s2);
        q2[2] = fmul2(bq.x, s2); q2[3] = fmul2(bq.y, s2);
        q2[4] = fmul2(c.x, s2);  q2[5] = fmul2(c.y, s2);
        q2[6] = fmul2(d.x, s2);  q2[7] = fmul2(d.y, s2);
    }

    // one-pass softmax-weighted AV (no max subtraction; masked -> p=0)
    u64 acc2[8];
#pragma unroll
    for (int t = 0; t < 8; t++) acc2[t] = 0ull;
    float ssum = 0.f;

#pragma unroll 4
    for (int j = 0; j < 64; j++) {
        const ulonglong2* kp = (const ulonglong2*)(k_s + j * 96 + co);
        ulonglong2 ka = kp[0], kb = kp[1], kc = kp[2], kd = kp[3];
        u64 d0 = 0ull, d1 = 0ull, d2 = 0ull, d3 = 0ull;
        d0 = ffma2(q2[0], ka.x, d0); d1 = ffma2(q2[1], ka.y, d1);
        d2 = ffma2(q2[2], kb.x, d2); d3 = ffma2(q2[3], kb.y, d3);
        d0 = ffma2(q2[4], kc.x, d0); d1 = ffma2(q2[5], kc.y, d1);
        d2 = ffma2(q2[6], kd.x, d2); d3 = ffma2(q2[7], kd.y, d3);
        float l0,h0,l1,h1,l2,h2,l3,h3;
        unpack2(d0,l0,h0); unpack2(d1,l1,h1); unpack2(d2,l2,h2); unpack2(d3,l3,h3);
        float s = ((l0+h0)+(l1+h1)) + ((l2+h2)+(l3+h3));
        const int joff = ((j >> 3) * 15 + (j & 7)) * 6;
        s += rpb_s[myoff - joff];
        const bool valid = (j != i) && (reg_s[j] == ri);
        float p = 0.f;
        if (valid) p = __expf(s);
        ssum += p;
        const u64 p2 = packdup(p);
        const ulonglong2* vp = (const ulonglong2*)(v_s + j * 96 + co);
        ulonglong2 va = vp[0], vb = vp[1], vc = vp[2], vd = vp[3];
        acc2[0] = ffma2(p2, va.x, acc2[0]); acc2[1] = ffma2(p2, va.y, acc2[1]);
        acc2[2] = ffma2(p2, vb.x, acc2[2]); acc2[3] = ffma2(p2, vb.y, acc2[3]);
        acc2[4] = ffma2(p2, vc.x, acc2[4]); acc2[5] = ffma2(p2, vc.y, acc2[5]);
        acc2[6] = ffma2(p2, vd.x, acc2[6]); acc2[7] = ffma2(p2, vd.y, acc2[7]);
    }

    {
        const u64 inv2 = packdup(1.0f / ssum);
#pragma unroll
        for (int t = 0; t < 8; t++) {
            u64 r2 = ffma2(acc2[t], inv2, q2[t]);   // + scaled-q residual
            float lo, hi; unpack2(r2, lo, hi);
            out_t[(co + 2*t    ) * 64 + i] = lo;
            out_t[(co + 2*t + 1) * 64 + i] = hi;
        }
    }
    __syncthreads();

    // LN (threads 0..63) || projW copy (threads 64..383, straight copy c-major)
    if (tid < 64) {
        float mu = 0.f;
#pragma unroll 8
        for (int c = 0; c < 96; c++) mu += out_t[c * 64 + tid];
        mu *= (1.0f / 96.0f);
        float var = 0.f;
#pragma unroll 8
        for (int c = 0; c < 96; c++) { const float d = out_t[c*64+tid] - mu; var = fmaf(d, d, var); }
        const float rs = rsqrtf(var * (1.0f / 96.0f) + 1e-5f);
#pragma unroll 8
        for (int c = 0; c < 96; c++)
            out_t[c*64+tid] = (out_t[c*64+tid] - mu) * rs * ng[c] + nb[c];
    } else {
        for (int n = tid - 64; n < 9216; n += 320) {
            const int c = n / 96, k = n - c * 96;
            w_s[c * 98 + k] = pw[n];
        }
    }
    __syncthreads();

    // proj GEMM: 4x4 tile, k-pair packed f32x2
    {
        const int r0 = (tid & 15) * 4;
        const int c0 = (tid >> 4) * 4;
        u64 a2[4][4];
#pragma unroll
        for (int r = 0; r < 4; r++)
#pragma unroll
            for (int c = 0; c < 4; c++) a2[r][c] = 0ull;

#pragma unroll 4
        for (int k = 0; k < 96; k += 2) {
            const float4 xa = *(const float4*)(out_t + k * 64 + r0);
            const float4 xb = *(const float4*)(out_t + (k + 1) * 64 + r0);
            u64 x0 = pack2(xa.x, xb.x), x1 = pack2(xa.y, xb.y);
            u64 x2 = pack2(xa.z, xb.z), x3 = pack2(xa.w, xb.w);
            u64 w0 = *(const u64*)(w_s + (c0 + 0) * 98 + k);
            u64 w1 = *(const u64*)(w_s + (c0 + 1) * 98 + k);
            u64 w2 = *(const u64*)(w_s + (c0 + 2) * 98 + k);
            u64 w3 = *(const u64*)(w_s + (c0 + 3) * 98 + k);
            a2[0][0]=ffma2(x0,w0,a2[0][0]); a2[0][1]=ffma2(x0,w1,a2[0][1]);
            a2[0][2]=ffma2(x0,w2,a2[0][2]); a2[0][3]=ffma2(x0,w3,a2[0][3]);
            a2[1][0]=ffma2(x1,w0,a2[1][0]); a2[1][1]=ffma2(x1,w1,a2[1][1]);
            a2[1][2]=ffma2(x1,w2,a2[1][2]); a2[1][3]=ffma2(x1,w3,a2[1][3]);
            a2[2][0]=ffma2(x2,w0,a2[2][0]); a2[2][1]=ffma2(x2,w1,a2[2][1]);
            a2[2][2]=ffma2(x2,w2,a2[2][2]); a2[2][3]=ffma2(x2,w3,a2[2][3]);
            a2[3][0]=ffma2(x3,w0,a2[3][0]); a2[3][1]=ffma2(x3,w1,a2[3][1]);
            a2[3][2]=ffma2(x3,w2,a2[3][2]); a2[3][3]=ffma2(x3,w3,a2[3][3]);
        }
        const float b0 = pb[c0+0], b1 = pb[c0+1], b2v = pb[c0+2], b3 = pb[c0+3];
#pragma unroll
        for (int r = 0; r < 4; r++) {
            float l0,h0,l1,h1,l2,h2,l3,h3;
            unpack2(a2[r][0],l0,h0); unpack2(a2[r][1],l1,h1);
            unpack2(a2[r][2],l2,h2); unpack2(a2[r][3],l3,h3);
            float4 o = make_float4(l0+h0+b0, l1+h1+b1, l2+h2+b2v, l3+h3+b3);
            *(float4*)(g_X + base_s[r0 + r] + c0) = o;
        }
    }
}

// ---- Kernel B: out = X + fc2(gelu(fc1(LN2(X)))), 128 pixels/block --------
// smem (floats):
//   w_s  [0,     9408)    96x98 (c_out-major)
//   x_s  [9408, 21824)    128x97 raw X tile / output staging
//   xn_t [21824,34112)    96x128 transposed normalized
//   h_t  [34112,46400)    96x128 transposed hidden
#define B_SMEM_FLOATS 46400

__global__ void __launch_bounds__(512, 1)
mlp_kernel(const float* __restrict__ n2g, const float* __restrict__ n2b,
           const float* __restrict__ w1, const float* __restrict__ b1,
           const float* __restrict__ w2, const float* __restrict__ b2,
           float* __restrict__ out)
{
    extern __shared__ float sm[];
    float* w_s  = sm;
    float* x_s  = sm + 9408;    // stride 97
    float* xn_t = sm + 21824;   // [c][row], stride 128
    float* h_t  = sm + 34112;   // [c][row], stride 128

    const int tid = threadIdx.x;
    const size_t p0 = (size_t)blockIdx.x * 128;
    const float* xg = g_X + p0 * 96;

    // load X tile (coalesced float4) -> x_s stride 97 (scalar stores)
    for (int n = tid; n < 3072; n += 512) {
        const int p = n / 24, c4 = n % 24;
        const float4 v = *(const float4*)(xg + n * 4);
        float* d = x_s + p * 97 + c4 * 4;
        d[0] = v.x; d[1] = v.y; d[2] = v.z; d[3] = v.w;
    }
    __syncthreads();

    // LN2 (threads 0..127, one pixel each, write transposed) || fc1W copy
    if (tid < 128) {
        const float* r = x_s + tid * 97;
        float mu = 0.f;
#pragma unroll 8
        for (int c = 0; c < 96; c++) mu += r[c];
        mu *= (1.0f / 96.0f);
        float var = 0.f;
#pragma unroll 8
        for (int c = 0; c < 96; c++) { const float d = r[c] - mu; var = fmaf(d, d, var); }
        const float rs = rsqrtf(var * (1.0f / 96.0f) + 1e-5f);
#pragma unroll 8
        for (int c = 0; c < 96; c++)
            xn_t[c * 128 + tid] = (r[c] - mu) * rs * n2g[c] + n2b[c];
    } else {
        for (int n = tid - 128; n < 9216; n += 384) {
            const int c = n / 96, k = n - c * 96;
            w_s[c * 98 + k] = w1[n];
        }
    }
    __syncthreads();

    const int r0 = (tid & 31) * 4;       // 32 row groups x 4
    const int c0 = (tid >> 5) * 6;       // 16 col groups x 6

    // GEMM1: h = gelu(xn @ fc1W^T + b1), k-pair packed
    {
        u64 a2[4][6];
#pragma unroll
        for (int r = 0; r < 4; r++)
#pragma unroll
            for (int c = 0; c < 6; c++) a2[r][c] = 0ull;

#pragma unroll 4
        for (int k = 0; k < 96; k += 2) {
            const float4 xa = *(const float4*)(xn_t + k * 128 + r0);
            const float4 xb = *(const float4*)(xn_t + (k + 1) * 128 + r0);
            u64 x0 = pack2(xa.x, xb.x), x1 = pack2(xa.y, xb.y);
            u64 x2 = pack2(xa.z, xb.z), x3 = pack2(xa.w, xb.w);
#pragma unroll
            for (int c = 0; c < 6; c++) {
                const u64 wv = *(const u64*)(w_s + (c0 + c) * 98 + k);
                a2[0][c] = ffma2(x0, wv, a2[0][c]);
                a2[1][c] = ffma2(x1, wv, a2[1][c]);
                a2[2][c] = ffma2(x2, wv, a2[2][c]);
                a2[3][c] = ffma2(x3, wv, a2[3][c]);
            }
        }
#pragma unroll
        for (int r = 0; r < 4; r++)
#pragma unroll
            for (int c = 0; c < 6; c++) {
                float lo, hi; unpack2(a2[r][c], lo, hi);
                float v = lo + hi + b1[c0 + c];
                v = 0.5f * v * (1.0f + erff(v * 0.70710678118654752440f));
                h_t[(c0 + c) * 128 + r0 + r] = v;
            }
    }
    __syncthreads();

    for (int n = tid; n < 9216; n += 512) {
        const int c = n / 96, k = n - c * 96;
        w_s[c * 98 + k] = w2[n];
    }
    __syncthreads();

    // GEMM2 + residual -> staged in x_s -> coalesced store
    {
        u64 a2[4][6];
#pragma unroll
        for (int r = 0; r < 4; r++)
#pragma unroll
            for (int c = 0; c < 6; c++) a2[r][c] = 0ull;

#pragma unroll 4
        for (int k = 0; k < 96; k += 2) {
            const float4 xa = *(const float4*)(h_t + k * 128 + r0);
            const float4 xb = *(const float4*)(h_t + (k + 1) * 128 + r0);
            u64 x0 = pack2(xa.x, xb.x), x1 = pack2(xa.y, xb.y);
            u64 x2 = pack2(xa.z, xb.z), x3 = pack2(xa.w, xb.w);
#pragma unroll
            for (int c = 0; c < 6; c++) {
                const u64 wv = *(const u64*)(w_s + (c0 + c) * 98 + k);
                a2[0][c] = ffma2(x0, wv, a2[0][c]);
                a2[1][c] = ffma2(x1, wv, a2[1][c]);
                a2[2][c] = ffma2(x2, wv, a2[2][c]);
                a2[3][c] = ffma2(x3, wv, a2[3][c]);
            }
        }
        float fin[4][6];
#pragma unroll
        for (int r = 0; r < 4; r++)
#pragma unroll
            for (int c = 0; c < 6; c++) {
                float lo, hi; unpack2(a2[r][c], lo, hi);
                fin[r][c] = lo + hi + b2[c0 + c] + x_s[(r0 + r) * 97 + c0 + c];
            }
        __syncthreads();
#pragma unroll
        for (int r = 0; r < 4; r++)
#pragma unroll
            for (int c = 0; c < 6; c++)
                x_s[(r0 + r) * 97 + c0 + c] = fin[r][c];
    }
    __syncthreads();

    // coalesced float4 store
    for (int n = tid; n < 3072; n += 512) {
        const int p = n / 24, c4 = n % 24;
        const float* s = x_s + p * 97 + c4 * 4;
        float4 o = make_float4(s[0], s[1], s[2], s[3]);
        *(float4*)(out + p0 * 96 + n * 4) = o;
    }
}

// ---------------------------------------------------------------------------
extern "C" void kernel_launch(void* const* d_in, const int* in_sizes, int n_in,
                              void* d_out, int out_size)
{
    const float* q   = (const float*)d_in[0];
    const float* k   = (const float*)d_in[1];
    const float* v   = (const float*)d_in[2];
    const float* rpb = (const float*)d_in[3];
    const float* ng  = (const float*)d_in[4];
    const float* nb  = (const float*)d_in[5];
    const float* pw  = (const float*)d_in[6];
    const float* pb  = (const float*)d_in[7];
    const float* n2g = (const float*)d_in[8];
    const float* n2b = (const float*)d_in[9];
    const float* w1  = (const float*)d_in[10];
    const float* b1  = (const float*)d_in[11];
    const float* w2  = (const float*)d_in[12];
    const float* b2  = (const float*)d_in[13];
    float* out = (float*)d_out;

    cudaFuncSetAttribute(attn_proj_kernel,
                         cudaFuncAttributeMaxDynamicSharedMemorySize,
                         A_SMEM_FLOATS * 4);
    cudaFuncSetAttribute(mlp_kernel,
                         cudaFuncAttributeMaxDynamicSharedMemorySize,
                         B_SMEM_FLOATS * 4);

    attn_proj_kernel<<<8192, 384, A_SMEM_FLOATS * 4>>>(q, k, v, rpb, ng, nb, pw, pb);
    mlp_kernel<<<4096, 512, B_SMEM_FLOATS * 4>>>(n2g, n2b, w1, b1, w2, b2, out);
}

// round 4
// speedup vs baseline: 1.0396x; 1.0396x over previous
#include <cuda_runtime.h>
#include <math.h>

// ---------------------------------------------------------------------------
// BlindSpotBlock: shifted-window blind-spot attention + proj + MLP
// B=8 H=256 W=256 C=96, WS=8 SS=4 NH=6 CH=16, NP=64, NW=1024, B*NW=8192
// f32x2 row-pairing, duplicated-weight LDG broadcast, zero packing movs.
// ---------------------------------------------------------------------------

#define NPIX (8*256*256)
typedef unsigned long long u64;

__device__ float g_X[NPIX * 96];        // attention-half output (B,H,W,C)
__device__ float g_Wd[3][96 * 96 * 2];  // [mat][(k*96+c)*2] = W[c][k] duplicated

__device__ __forceinline__ u64 pack2(float lo, float hi){
    u64 r; asm("mov.b64 %0, {%1, %2};" : "=l"(r) : "f"(lo), "f"(hi)); return r;
}
__device__ __forceinline__ u64 packdup(float x){
    u64 r; asm("mov.b64 %0, {%1, %1};" : "=l"(r) : "f"(x)); return r;
}
__device__ __forceinline__ void unpack2(u64 v, float& lo, float& hi){
    asm("mov.b64 {%0, %1}, %2;" : "=f"(lo), "=f"(hi) : "l"(v));
}
__device__ __forceinline__ u64 ffma2(u64 a, u64 b, u64 c){
    u64 d; asm("fma.rn.f32x2 %0, %1, %2, %3;" : "=l"(d) : "l"(a), "l"(b), "l"(c)); return d;
}
__device__ __forceinline__ u64 fmul2(u64 a, u64 b){
    u64 d; asm("mul.rn.f32x2 %0, %1, %2;" : "=l"(d) : "l"(a), "l"(b)); return d;
}
__device__ __forceinline__ u64 fadd2(u64 a, u64 b){
    u64 d; asm("add.rn.f32x2 %0, %1, %2;" : "=l"(d) : "l"(a), "l"(b)); return d;
}

// ---- prep: transpose + duplicate the three 96x96 weight matrices ----------
__global__ void prep_kernel(const float* __restrict__ pw,
                            const float* __restrict__ w1,
                            const float* __restrict__ w2)
{
    int n = blockIdx.x * 256 + threadIdx.x;
    if (n < 9216) {
        const int c = n / 96, k = n - c * 96;
        const int o = (k * 96 + c) * 2;
        float a = pw[n]; g_Wd[0][o] = a; g_Wd[0][o + 1] = a;
        float b = w1[n]; g_Wd[1][o] = b; g_Wd[1][o + 1] = b;
        float d = w2[n]; g_Wd[2][o] = d; g_Wd[2][o + 1] = d;
    }
}

// ---- Kernel A: attention + LN + proj --------------------------------------
// smem (floats): k_s[0,6144) v_s[6144,12288) rpb[12288,13638)
//                base[13640..] reg[13704..]; out_t overlays [0,6144) post-sync
#define A_SMEM_FLOATS 13768

__global__ void __launch_bounds__(384, 2)
attn_proj_kernel(const float* __restrict__ q_in,
                 const float* __restrict__ k_in,
                 const float* __restrict__ v_in,
                 const float* __restrict__ rpb,
                 const float* __restrict__ ng,
                 const float* __restrict__ nb,
                 const float* __restrict__ pb)
{
    extern __shared__ float sm[];
    float* k_s    = sm;
    float* v_s    = sm + 6144;
    float* rpb_s  = sm + 12288;
    int*   base_s = (int*)(sm + 13640);
    int*   reg_s  = (int*)(sm + 13704);
    float* out_t  = sm;                 // [c][row] stride 64, reused post-sync

    const int tid  = threadIdx.x;
    const int w    = blockIdx.x;
    const int b    = w >> 10;
    const int widx = w & 1023;
    const int wy   = widx >> 5;
    const int wx   = widx & 31;

    if (tid < 64) {
        const int py = tid >> 3, px = tid & 7;
        const int ys = (wy * 8 + py + 4) & 255;
        const int xs = (wx * 8 + px + 4) & 255;
        base_s[tid] = ((b * 256 + ys) * 256 + xs) * 96;
        const int row = wy * 8 + py, col = wx * 8 + px;
        const int rr = (row < 248) ? 0 : ((row < 252) ? 1 : 2);
        const int cr = (col < 248) ? 0 : ((col < 252) ? 1 : 2);
        reg_s[tid] = rr * 3 + cr;
    }
    for (int n = tid; n < 1350; n += 384) rpb_s[n] = rpb[n];
    __syncthreads();

    // gather K/V window tiles (coalesced float4)
    for (int n = tid; n < 1536; n += 384) {
        const int p = n / 24, c4 = n - p * 24;
        const int g = base_s[p] + c4 * 4;
        *(float4*)(k_s + p * 96 + c4 * 4) = *(const float4*)(k_in + g);
        *(float4*)(v_s + p * 96 + c4 * 4) = *(const float4*)(v_in + g);
    }
    __syncthreads();

    // thread = (head hh, query row i)
    const int hh = tid >> 6;
    const int i  = tid & 63;
    const int co = hh * 16;
    const int yi = i >> 3, xi = i & 7;
    const int ri = reg_s[i];
    const int myoff = (112 + yi * 15 + xi) * 6 + hh;

    // q scaled, channel-pairs (aligned loads)
    u64 q2[8];
    {
        const ulonglong2* qp = (const ulonglong2*)(q_in + base_s[i] + co);
        const u64 s2 = packdup(0.25f);
        ulonglong2 a = qp[0], bq = qp[1], c = qp[2], d = qp[3];
        q2[0] = fmul2(a.x, s2);  q2[1] = fmul2(a.y, s2);
        q2[2] = fmul2(bq.x, s2); q2[3] = fmul2(bq.y, s2);
        q2[4] = fmul2(c.x, s2);  q2[5] = fmul2(c.y, s2);
        q2[6] = fmul2(d.x, s2);  q2[7] = fmul2(d.y, s2);
    }

    u64 acc2[8];
#pragma unroll
    for (int t = 0; t < 8; t++) acc2[t] = 0ull;
    float ssum = 0.f;

#pragma unroll 8
    for (int j = 0; j < 64; j++) {
        const ulonglong2* kp = (const ulonglong2*)(k_s + j * 96 + co);
        ulonglong2 ka = kp[0], kb = kp[1], kc = kp[2], kd = kp[3];
        u64 d0 = 0ull, d1 = 0ull, d2 = 0ull, d3 = 0ull;
        d0 = ffma2(q2[0], ka.x, d0); d1 = ffma2(q2[1], ka.y, d1);
        d2 = ffma2(q2[2], kb.x, d2); d3 = ffma2(q2[3], kb.y, d3);
        d0 = ffma2(q2[4], kc.x, d0); d1 = ffma2(q2[5], kc.y, d1);
        d2 = ffma2(q2[6], kd.x, d2); d3 = ffma2(q2[7], kd.y, d3);
        u64 e = fadd2(fadd2(d0, d1), fadd2(d2, d3));
        float lo, hi; unpack2(e, lo, hi);
        float s = lo + hi;
        s += rpb_s[myoff - ((j >> 3) * 15 + (j & 7)) * 6];
        const bool valid = (j != i) && (reg_s[j] == ri);
        float p = valid ? __expf(s) : 0.f;
        ssum += p;
        const u64 p2 = packdup(p);
        const ulonglong2* vp = (const ulonglong2*)(v_s + j * 96 + co);
        ulonglong2 va = vp[0], vb = vp[1], vc = vp[2], vd = vp[3];
        acc2[0] = ffma2(p2, va.x, acc2[0]); acc2[1] = ffma2(p2, va.y, acc2[1]);
        acc2[2] = ffma2(p2, vb.x, acc2[2]); acc2[3] = ffma2(p2, vb.y, acc2[3]);
        acc2[4] = ffma2(p2, vc.x, acc2[4]); acc2[5] = ffma2(p2, vc.y, acc2[5]);
        acc2[6] = ffma2(p2, vd.x, acc2[6]); acc2[7] = ffma2(p2, vd.y, acc2[7]);
    }

    u64 res2[8];
    {
        const u64 inv2 = packdup(1.0f / ssum);
#pragma unroll
        for (int t = 0; t < 8; t++) res2[t] = ffma2(acc2[t], inv2, q2[t]);
    }
    __syncthreads();          // all k_s/v_s reads done; out_t may overlay

#pragma unroll
    for (int t = 0; t < 8; t++) {
        float lo, hi; unpack2(res2[t], lo, hi);
        out_t[(co + 2 * t    ) * 64 + i] = lo;
        out_t[(co + 2 * t + 1) * 64 + i] = hi;
    }
    __syncthreads();

    // LayerNorm: threads 0..63, one pixel each, column reads (conflict-free)
    if (tid < 64) {
        float s1 = 0.f, s2v = 0.f;
#pragma unroll 8
        for (int c = 0; c < 96; c++) {
            const float x = out_t[c * 64 + tid];
            s1 += x; s2v = fmaf(x, x, s2v);
        }
        const float mu = s1 * (1.0f / 96.0f);
        const float var = s2v * (1.0f / 96.0f) - mu * mu;
        const float rs = rsqrtf(var + 1e-5f);
#pragma unroll 8
        for (int c = 0; c < 96; c++)
            out_t[c * 64 + tid] = (out_t[c * 64 + tid] - mu) * rs * ng[c] + nb[c];
    }
    __syncthreads();

    // proj GEMM: row-pair f32x2, dup weights via LDG broadcast
    {
        const int rg = tid & 15, cg = tid >> 4;
        const int r0 = rg * 4, c0 = cg * 4;
        const float* wd = g_Wd[0];
        u64 acc[2][4];
#pragma unroll
        for (int c = 0; c < 4; c++) {
            const u64 bb = packdup(pb[c0 + c]);
            acc[0][c] = bb; acc[1][c] = bb;
        }
#pragma unroll 4
        for (int k = 0; k < 96; k++) {
            const ulonglong2 xu = *(const ulonglong2*)(out_t + k * 64 + r0);
#pragma unroll
            for (int c = 0; c < 4; c++) {
                const u64 wv = *(const u64*)(wd + (k * 96 + c0 + c) * 2);
                acc[0][c] = ffma2(xu.x, wv, acc[0][c]);
                acc[1][c] = ffma2(xu.y, wv, acc[1][c]);
            }
        }
        float l[2][4], h[2][4];
#pragma unroll
        for (int pr = 0; pr < 2; pr++)
#pragma unroll
            for (int c = 0; c < 4; c++) unpack2(acc[pr][c], l[pr][c], h[pr][c]);
        *(float4*)(g_X + base_s[r0 + 0] + c0) = make_float4(l[0][0], l[0][1], l[0][2], l[0][3]);
        *(float4*)(g_X + base_s[r0 + 1] + c0) = make_float4(h[0][0], h[0][1], h[0][2], h[0][3]);
        *(float4*)(g_X + base_s[r0 + 2] + c0) = make_float4(l[1][0], l[1][1], l[1][2], l[1][3]);
        *(float4*)(g_X + base_s[r0 + 3] + c0) = make_float4(h[1][0], h[1][1], h[1][2], h[1][3]);
    }
}

// ---- Kernel B: out = X + fc2(gelu(fc1(LN2(X)))) ---------------------------
// 64 pixels/block, 128 threads, 4 CTAs/SM
// smem: xn_t[96][68] @0, h_t[96][68] @6528
#define B_SMEM_FLOATS 13056

__global__ void __launch_bounds__(128, 4)
mlp_kernel(const float* __restrict__ n2g, const float* __restrict__ n2b,
           const float* __restrict__ b1,  const float* __restrict__ b2,
           float* __restrict__ out)
{
    extern __shared__ float sm[];
    float* xn_t = sm;            // [c][p] stride 68
    float* h_t  = sm + 6528;

    const int tid = threadIdx.x;
    const size_t p0 = (size_t)blockIdx.x * 64;
    const float* xg = g_X + p0 * 96;

    // load X coalesced -> transposed
    for (int n = tid; n < 1536; n += 128) {
        const int p = n / 24, c4 = n - p * 24;
        const float4 v = *(const float4*)(xg + n * 4);
        xn_t[(c4 * 4 + 0) * 68 + p] = v.x;
        xn_t[(c4 * 4 + 1) * 68 + p] = v.y;
        xn_t[(c4 * 4 + 2) * 68 + p] = v.z;
        xn_t[(c4 * 4 + 3) * 68 + p] = v.w;
    }
    __syncthreads();

    // LN2 in place: threads 0..63 (column reads conflict-free)
    if (tid < 64) {
        float s1 = 0.f, s2v = 0.f;
#pragma unroll 8
        for (int c = 0; c < 96; c++) {
            const float x = xn_t[c * 68 + tid];
            s1 += x; s2v = fmaf(x, x, s2v);
        }
        const float mu = s1 * (1.0f / 96.0f);
        const float var = s2v * (1.0f / 96.0f) - mu * mu;
        const float rs = rsqrtf(var + 1e-5f);
#pragma unroll 8
        for (int c = 0; c < 96; c++)
            xn_t[c * 68 + tid] = (xn_t[c * 68 + tid] - mu) * rs * n2g[c] + n2b[c];
    }
    __syncthreads();

    const int rg = tid & 7, cg = tid >> 3;
    const int r0 = rg * 8, c0 = cg * 6;

    // GEMM1: h = gelu(xn @ W1^T + b1); 8 rows x 6 cols, row-pair f32x2
    {
        const float* wd = g_Wd[1];
        u64 acc[4][6];
#pragma unroll
        for (int c = 0; c < 6; c++) {
            const u64 bb = packdup(b1[c0 + c]);
            acc[0][c] = bb; acc[1][c] = bb; acc[2][c] = bb; acc[3][c] = bb;
        }
#pragma unroll 4
        for (int k = 0; k < 96; k++) {
            const ulonglong2 xa = *(const ulonglong2*)(xn_t + k * 68 + r0);
            const ulonglong2 xb = *(const ulonglong2*)(xn_t + k * 68 + r0 + 4);
#pragma unroll
            for (int c = 0; c < 6; c++) {
                const u64 wv = *(const u64*)(wd + (k * 96 + c0 + c) * 2);
                acc[0][c] = ffma2(xa.x, wv, acc[0][c]);
                acc[1][c] = ffma2(xa.y, wv, acc[1][c]);
                acc[2][c] = ffma2(xb.x, wv, acc[2][c]);
                acc[3][c] = ffma2(xb.y, wv, acc[3][c]);
            }
        }
#pragma unroll
        for (int pr = 0; pr < 4; pr++)
#pragma unroll
            for (int c = 0; c < 6; c++) {
                float lo, hi; unpack2(acc[pr][c], lo, hi);
                lo = 0.5f * lo * (1.0f + erff(lo * 0.70710678118654752440f));
                hi = 0.5f * hi * (1.0f + erff(hi * 0.70710678118654752440f));
                *(u64*)(h_t + (c0 + c) * 68 + r0 + pr * 2) = pack2(lo, hi);
            }
    }
    __syncthreads();

    // GEMM2 + residual, staged back into xn_t for coalesced store
    {
        const float* wd = g_Wd[2];
        u64 acc[4][6];
#pragma unroll
        for (int c = 0; c < 6; c++) {
            const u64 bb = packdup(b2[c0 + c]);
            acc[0][c] = bb; acc[1][c] = bb; acc[2][c] = bb; acc[3][c] = bb;
        }
#pragma unroll 4
        for (int k = 0; k < 96; k++) {
            const ulonglong2 xa = *(const ulonglong2*)(h_t + k * 68 + r0);
            const ulonglong2 xb = *(const ulonglong2*)(h_t + k * 68 + r0 + 4);
#pragma unroll
            for (int c = 0; c < 6; c++) {
                const u64 wv = *(const u64*)(wd + (k * 96 + c0 + c) * 2);
                acc[0][c] = ffma2(xa.x, wv, acc[0][c]);
                acc[1][c] = ffma2(xa.y, wv, acc[1][c]);
                acc[2][c] = ffma2(xb.x, wv, acc[2][c]);
                acc[3][c] = ffma2(xb.y, wv, acc[3][c]);
            }
        }
#pragma unroll
        for (int pr = 0; pr < 4; pr++) {
            const int ra = r0 + pr * 2, rb = ra + 1;
            const float2* xra = (const float2*)(g_X + (p0 + ra) * 96 + c0);
            const float2* xrb = (const float2*)(g_X + (p0 + rb) * 96 + c0);
#pragma unroll
            for (int m = 0; m < 3; m++) {
                const float2 ea = xra[m], eb = xrb[m];
                float l0, h0, l1, h1;
                unpack2(acc[pr][2 * m    ], l0, h0);
                unpack2(acc[pr][2 * m + 1], l1, h1);
                // acc pair = {row ra, row rb} at col (c0+2m) / (c0+2m+1)
                *(u64*)(xn_t + (c0 + 2 * m    ) * 68 + ra) = pack2(l0 + ea.x, h0 + eb.x);
                *(u64*)(xn_t + (c0 + 2 * m + 1) * 68 + ra) = pack2(l1 + ea.y, h1 + eb.y);
            }
        }
    }
    __syncthreads();

    // coalesced float4 store from staged xn_t
    for (int n = tid; n < 1536; n += 128) {
        const int p = n / 24, c4 = n - p * 24;
        float4 o;
        o.x = xn_t[(c4 * 4 + 0) * 68 + p];
        o.y = xn_t[(c4 * 4 + 1) * 68 + p];
        o.z = xn_t[(c4 * 4 + 2) * 68 + p];
        o.w = xn_t[(c4 * 4 + 3) * 68 + p];
        *(float4*)(out + (p0 + p) * 96 + c4 * 4) = o;
    }
}

// ---------------------------------------------------------------------------
extern "C" void kernel_launch(void* const* d_in, const int* in_sizes, int n_in,
                              void* d_out, int out_size)
{
    const float* q   = (const float*)d_in[0];
    const float* k   = (const float*)d_in[1];
    const float* v   = (const float*)d_in[2];
    const float* rpb = (const float*)d_in[3];
    const float* ng  = (const float*)d_in[4];
    const float* nb  = (const float*)d_in[5];
    const float* pw  = (const float*)d_in[6];
    const float* pb  = (const float*)d_in[7];
    const float* n2g = (const float*)d_in[8];
    const float* n2b = (const float*)d_in[9];
    const float* w1  = (const float*)d_in[10];
    const float* b1  = (const float*)d_in[11];
    const float* w2  = (const float*)d_in[12];
    const float* b2  = (const float*)d_in[13];
    float* out = (float*)d_out;

    cudaFuncSetAttribute(attn_proj_kernel,
                         cudaFuncAttributeMaxDynamicSharedMemorySize,
                         A_SMEM_FLOATS * 4);
    cudaFuncSetAttribute(mlp_kernel,
                         cudaFuncAttributeMaxDynamicSharedMemorySize,
                         B_SMEM_FLOATS * 4);

    prep_kernel<<<36, 256>>>(pw, w1, w2);
    attn_proj_kernel<<<8192, 384, A_SMEM_FLOATS * 4>>>(q, k, v, rpb, ng, nb, pb);
    mlp_kernel<<<8192, 128, B_SMEM_FLOATS * 4>>>(n2g, n2b, b1, b2, out);
}

// round 8
// speedup vs baseline: 1.1914x; 1.1460x over previous
#include <cuda_runtime.h>
#include <cuda_bf16.h>
#include <cstdint>
#include <math.h>

// ---------------------------------------------------------------------------
// BlindSpotBlock: B=8 H=256 W=256 C=96, WS=8 SS=4 NH=6 CH=16
// attention: SIMT.  proj/fc1/fc2: mma.sync bf16x3 split GEMM (fp32-accurate).
// Rows kept window-linear; scatter only at the very end.
// ---------------------------------------------------------------------------

#define NROWS 524288              // B*NW*64 window-linear rows
#define KEXT  288                 // 96(hi) + 96(lo) + 96(hi); 18 k16 steps
#define NSTEP 18

__device__ __nv_bfloat16 g_ext[(size_t)NROWS * KEXT];   // A_ext rows (reused in-place)
__device__ float         g_X[(size_t)NROWS * 96];       // proj output X (window-linear)
__device__ __nv_bfloat16 g_Wext[3][96 * KEXT];          // W_ext per matrix

typedef unsigned long long u64;

__device__ __forceinline__ uint32_t smem_u32(const void* p){
    uint32_t a;
    asm("{ .reg .u64 t; cvta.to.shared.u64 t, %1; cvt.u32.u64 %0, t; }" : "=r"(a) : "l"(p));
    return a;
}
__device__ __forceinline__ uint4 ldmat4(uint32_t a){
    uint4 r;
    asm volatile("ldmatrix.sync.aligned.m8n8.x4.shared.b16 {%0,%1,%2,%3}, [%4];"
                 : "=r"(r.x), "=r"(r.y), "=r"(r.z), "=r"(r.w) : "r"(a));
    return r;
}
__device__ __forceinline__ void mma_bf16(float* d, const uint4 a, uint32_t b0, uint32_t b1){
    asm volatile("mma.sync.aligned.m16n8k16.row.col.f32.bf16.bf16.f32 "
                 "{%0,%1,%2,%3}, {%4,%5,%6,%7}, {%8,%9}, {%0,%1,%2,%3};"
                 : "+f"(d[0]), "+f"(d[1]), "+f"(d[2]), "+f"(d[3])
                 : "r"(a.x), "r"(a.y), "r"(a.z), "r"(a.w), "r"(b0), "r"(b1));
}
// pack two floats to bf16x2 (hi if lo==0, residual if lo==1)
__device__ __forceinline__ unsigned bfpack(float a, float b, int lo){
    __nv_bfloat16 ha = __float2bfloat16(a), hb = __float2bfloat16(b);
    if (lo) {
        ha = __float2bfloat16(a - __bfloat162float(ha));
        hb = __float2bfloat16(b - __bfloat162float(hb));
    }
    return (unsigned)__bfloat16_as_ushort(ha) | ((unsigned)__bfloat16_as_ushort(hb) << 16);
}

// ---------------- prep: build W_ext = [Wh | Wh | Wl] -----------------------
__global__ void prep_wext(const float* __restrict__ pw,
                          const float* __restrict__ w1,
                          const float* __restrict__ w2)
{
    const int c = blockIdx.x;      // 0..95 output channel
    const int k = threadIdx.x;     // 0..95
    const float* src[3] = {pw, w1, w2};
#pragma unroll
    for (int m = 0; m < 3; m++) {
        const float wv = src[m][c * 96 + k];
        __nv_bfloat16 bh = __float2bfloat16(wv);
        __nv_bfloat16 bl = __float2bfloat16(wv - __bfloat162float(bh));
        g_Wext[m][c * KEXT + k]       = bh;
        g_Wext[m][c * KEXT + 96 + k]  = bh;
        g_Wext[m][c * KEXT + 192 + k] = bl;
    }
}

// ---------------- Kernel A: attention + LN1 -> g_ext (window-linear) -------
#define A_SMEM_FLOATS 19974
__global__ void __launch_bounds__(384, 2)
attn_kernel(const float* __restrict__ q_in,
            const float* __restrict__ k_in,
            const float* __restrict__ v_in,
            const float* __restrict__ rpb,
            const float* __restrict__ ng,
            const float* __restrict__ nb)
{
    extern __shared__ float sm[];
    float* k_s    = sm;
    float* v_s    = sm + 6144;
    float* out_s  = sm + 12288;      // 64 x 97
    float* rpb_s  = sm + 18496;
    int*   base_s = (int*)(sm + 19846);
    int*   reg_s  = (int*)(sm + 19910);

    const int tid  = threadIdx.x;
    const int w    = blockIdx.x;
    const int b    = w >> 10;
    const int widx = w & 1023;
    const int wy   = widx >> 5;
    const int wx   = widx & 31;

    if (tid < 64) {
        const int py = tid >> 3, px = tid & 7;
        const int ys = (wy * 8 + py + 4) & 255;
        const int xs = (wx * 8 + px + 4) & 255;
        base_s[tid] = ((b * 256 + ys) * 256 + xs) * 96;
        const int row = wy * 8 + py, col = wx * 8 + px;
        const int rr = (row < 248) ? 0 : ((row < 252) ? 1 : 2);
        const int cr = (col < 248) ? 0 : ((col < 252) ? 1 : 2);
        reg_s[tid] = rr * 3 + cr;
    }
    for (int n = tid; n < 1350; n += 384) rpb_s[n] = rpb[n];
    __syncthreads();

    for (int n = tid; n < 1536; n += 384) {
        const int p = n / 24, c4 = n - p * 24;
        const int g = base_s[p] + c4 * 4;
        *(float4*)(k_s + p * 96 + c4 * 4) = *(const float4*)(k_in + g);
        *(float4*)(v_s + p * 96 + c4 * 4) = *(const float4*)(v_in + g);
    }
    __syncthreads();

    const int hh = tid >> 6;
    const int i  = tid & 63;
    const int co = hh * 16;
    const int yi = i >> 3, xi = i & 7;
    const int ri = reg_s[i];
    const int myoff = (112 + yi * 15 + xi) * 6 + hh;

    float qv[16];
    {
        const float4* qp = (const float4*)(q_in + base_s[i] + co);
        float4 a = qp[0], bq = qp[1], c = qp[2], d = qp[3];
        qv[0]=a.x*0.25f; qv[1]=a.y*0.25f; qv[2]=a.z*0.25f; qv[3]=a.w*0.25f;
        qv[4]=bq.x*0.25f; qv[5]=bq.y*0.25f; qv[6]=bq.z*0.25f; qv[7]=bq.w*0.25f;
        qv[8]=c.x*0.25f; qv[9]=c.y*0.25f; qv[10]=c.z*0.25f; qv[11]=c.w*0.25f;
        qv[12]=d.x*0.25f; qv[13]=d.y*0.25f; qv[14]=d.z*0.25f; qv[15]=d.w*0.25f;
    }

    float acc[16];
#pragma unroll
    for (int c = 0; c < 16; c++) acc[c] = 0.f;
    float ssum = 0.f;

#pragma unroll 4
    for (int j = 0; j < 64; j++) {
        const float4* kp = (const float4*)(k_s + j * 96 + co);
        float4 k0 = kp[0], k1 = kp[1], k2 = kp[2], k3 = kp[3];
        float s0 = fmaf(qv[0], k0.x, fmaf(qv[1], k0.y, fmaf(qv[2], k0.z, qv[3] * k0.w)));
        float s1 = fmaf(qv[4], k1.x, fmaf(qv[5], k1.y, fmaf(qv[6], k1.z, qv[7] * k1.w)));
        float s2 = fmaf(qv[8], k2.x, fmaf(qv[9], k2.y, fmaf(qv[10], k2.z, qv[11] * k2.w)));
        float s3 = fmaf(qv[12], k3.x, fmaf(qv[13], k3.y, fmaf(qv[14], k3.z, qv[15] * k3.w)));
        float s = (s0 + s1) + (s2 + s3);
        s += rpb_s[myoff - ((j >> 3) * 15 + (j & 7)) * 6];
        const float p = ((j != i) && (reg_s[j] == ri)) ? __expf(s) : 0.f;
        ssum += p;
        const float4* vp = (const float4*)(v_s + j * 96 + co);
        float4 v0 = vp[0], v1 = vp[1], v2 = vp[2], v3 = vp[3];
        acc[0]=fmaf(p,v0.x,acc[0]); acc[1]=fmaf(p,v0.y,acc[1]); acc[2]=fmaf(p,v0.z,acc[2]); acc[3]=fmaf(p,v0.w,acc[3]);
        acc[4]=fmaf(p,v1.x,acc[4]); acc[5]=fmaf(p,v1.y,acc[5]); acc[6]=fmaf(p,v1.z,acc[6]); acc[7]=fmaf(p,v1.w,acc[7]);
        acc[8]=fmaf(p,v2.x,acc[8]); acc[9]=fmaf(p,v2.y,acc[9]); acc[10]=fmaf(p,v2.z,acc[10]); acc[11]=fmaf(p,v2.w,acc[11]);
        acc[12]=fmaf(p,v3.x,acc[12]); acc[13]=fmaf(p,v3.y,acc[13]); acc[14]=fmaf(p,v3.z,acc[14]); acc[15]=fmaf(p,v3.w,acc[15]);
    }

    const float inv = 1.0f / ssum;
#pragma unroll
    for (int c = 0; c < 16; c++)
        out_s[i * 97 + co + c] = fmaf(acc[c], inv, qv[c]);
    __syncthreads();

    // LayerNorm1 (threads 0..63)
    if (tid < 64) {
        float* r = out_s + tid * 97;
        float s1 = 0.f, s2 = 0.f;
#pragma unroll 8
        for (int c = 0; c < 96; c++) { const float x = r[c]; s1 += x; s2 = fmaf(x, x, s2); }
        const float mu = s1 * (1.0f / 96.0f);
        const float var = s2 * (1.0f / 96.0f) - mu * mu;
        const float rs = rsqrtf(var + 1e-5f);
#pragma unroll 8
        for (int c = 0; c < 96; c++)
            r[c] = (r[c] - mu) * rs * ng[c] + nb[c];
    }
    __syncthreads();

    // write ext rows (hi | lo | hi), coalesced uint4 (36 per row)
    uint4* dst = (uint4*)(g_ext + (size_t)w * 64 * KEXT);
    for (int n = tid; n < 2304; n += 384) {
        const int p = n / 36, m = n - p * 36;
        const int blk = (m >= 12 && m < 24) ? 1 : 0;
        const int cb = (m % 12) * 8;
        const float* r = out_s + p * 97 + cb;
        uint4 u;
        u.x = bfpack(r[0], r[1], blk);
        u.y = bfpack(r[2], r[3], blk);
        u.z = bfpack(r[4], r[5], blk);
        u.w = bfpack(r[6], r[7], blk);
        dst[n] = u;
    }
}

// ---------------- HMMA split-GEMM kernel -----------------------------------
// C[128 x 96] = A_ext[128 x 288] @ W_ext[96 x 288]^T  (bf16 in, fp32 accum)
// mode 0: proj -> store X, LN2 -> ext rows (in-place)
// mode 1: fc1  -> gelu -> ext rows (in-place)
// mode 2: fc2  -> + bias + X residual -> scatter to final out
#define TILE_STRIDE_B 592            // bytes per smem row (296 bf16)
#define SM_A   0                     // 128 rows  -> 75776 B
#define SM_W   75776                 // 96 rows   -> 56832 B
#define SM_TOTAL 132608
#define CSTG_STRIDE 100              // floats

__global__ void __launch_bounds__(256, 1)
gemm_ext_kernel(int mode, int wmat,
                const float* __restrict__ bias,
                const float* __restrict__ gam,
                const float* __restrict__ bet,
                float* __restrict__ outp)
{
    extern __shared__ char smem[];
    const uint32_t sbase = smem_u32(smem);
    const int tid  = threadIdx.x;
    const int wid  = tid >> 5, lane = tid & 31;
    const long rowbase = (long)blockIdx.x * 128;

    // ---- load A (128 x 288 bf16) and W (96 x 288 bf16) into padded smem ----
    {
        const uint4* Ag = (const uint4*)(g_ext + rowbase * KEXT);
        for (int n = tid; n < 4608; n += 256) {
            const int r = n / 36, m = n - r * 36;
            *(uint4*)(smem + SM_A + r * TILE_STRIDE_B + m * 16) = Ag[n];
        }
        const uint4* Wg = (const uint4*)(&g_Wext[wmat][0]);
        for (int n = tid; n < 3456; n += 256) {
            const int r = n / 36, m = n - r * 36;
            *(uint4*)(smem + SM_W + r * TILE_STRIDE_B + m * 16) = Wg[n];
        }
    }
    __syncthreads();

    // ---- MMA mainloop: warp wid -> rows [wid*16, wid*16+16) ----------------
    float accf[12][4];
#pragma unroll
    for (int t = 0; t < 12; t++)
#pragma unroll
        for (int e = 0; e < 4; e++) accf[t][e] = 0.f;

    {
        const int m0 = wid * 16;
        const uint32_t aBase = sbase + SM_A + (uint32_t)(m0 + (lane & 15)) * TILE_STRIDE_B
                             + (uint32_t)(lane >> 4) * 16;
        const int j = lane >> 3;
        const uint32_t bBase = sbase + SM_W
                             + (uint32_t)(((j >> 1) * 8) + (lane & 7)) * TILE_STRIDE_B
                             + (uint32_t)(j & 1) * 16;
#pragma unroll 2
        for (int ks = 0; ks < NSTEP; ks++) {
            const uint4 a = ldmat4(aBase + ks * 32);
#pragma unroll
            for (int nt = 0; nt < 6; nt++) {
                const uint4 bf = ldmat4(bBase + nt * (16 * TILE_STRIDE_B) + ks * 32);
                mma_bf16(accf[2 * nt    ], a, bf.x, bf.y);
                mma_bf16(accf[2 * nt + 1], a, bf.z, bf.w);
            }
        }
    }
    __syncthreads();        // smem A/W free after this

    // ---- store C fragments to Cstg (in W region) ---------------------------
    float* Cstg = (float*)(smem + SM_W);
    {
        const int m0 = wid * 16;
        const int gr = lane >> 2, gc = (lane & 3) * 2;
#pragma unroll
        for (int t = 0; t < 12; t++) {
            *(float2*)(Cstg + (m0 + gr    ) * CSTG_STRIDE + t * 8 + gc) = make_float2(accf[t][0], accf[t][1]);
            *(float2*)(Cstg + (m0 + gr + 8) * CSTG_STRIDE + t * 8 + gc) = make_float2(accf[t][2], accf[t][3]);
        }
    }
    // mode 2: cooperatively load X tile into A region (stride 148 floats)
    float* Astgf = (float*)(smem + SM_A);
    if (mode == 2) {
        const float* Xg = g_X + rowbase * 96;
        for (int n = tid; n < 3072; n += 256) {
            const int r = n / 24, c4 = n - r * 24;
            const float4 v = *(const float4*)(Xg + n * 4);
            *(float4*)(Astgf + r * 148 + c4 * 4) = v;
        }
    }
    __syncthreads();

    // ---- per-row epilogue (threads 0..127 own one row each) ----------------
    unsigned* Astgu = (unsigned*)(smem + SM_A);
    if (tid < 128) {
        const int r = tid;
        float x[96];
#pragma unroll 8
        for (int c = 0; c < 96; c++) x[c] = Cstg[r * CSTG_STRIDE + c] + bias[c];

        if (mode == 0) {
            // stash raw X back into Cstg row (row-private), then LN2
#pragma unroll 8
            for (int c = 0; c < 96; c++) Cstg[r * CSTG_STRIDE + c] = x[c];
            float s1 = 0.f, s2 = 0.f;
#pragma unroll 8
            for (int c = 0; c < 96; c++) { s1 += x[c]; s2 = fmaf(x[c], x[c], s2); }
            const float mu = s1 * (1.0f / 96.0f);
            const float var = s2 * (1.0f / 96.0f) - mu * mu;
            const float rs = rsqrtf(var + 1e-5f);
#pragma unroll 8
            for (int c = 0; c < 96; c++) x[c] = (x[c] - mu) * rs * gam[c] + bet[c];
        } else if (mode == 1) {
#pragma unroll 4
            for (int c = 0; c < 96; c++) {
                const float v = x[c];
                x[c] = 0.5f * v * (1.0f + erff(v * 0.70710678118654752440f));
            }
        } else {
#pragma unroll 8
            for (int c = 0; c < 96; c++) x[c] += Astgf[r * 148 + c];
        }

        if (mode <= 1) {
            // stage ext row: [hi(12) | lo(12) | hi(12)] uint4
            unsigned* st = Astgu + r * 148;
#pragma unroll
            for (int m = 0; m < 12; m++) {
                uint4 u;
                u.x = bfpack(x[m*8+0], x[m*8+1], 0);
                u.y = bfpack(x[m*8+2], x[m*8+3], 0);
                u.z = bfpack(x[m*8+4], x[m*8+5], 0);
                u.w = bfpack(x[m*8+6], x[m*8+7], 0);
                *(uint4*)(st + m * 4) = u;
                *(uint4*)(st + (24 + m) * 4) = u;
            }
#pragma unroll
            for (int m = 0; m < 12; m++) {
                uint4 u;
                u.x = bfpack(x[m*8+0], x[m*8+1], 1);
                u.y = bfpack(x[m*8+2], x[m*8+3], 1);
                u.z = bfpack(x[m*8+4], x[m*8+5], 1);
                u.w = bfpack(x[m*8+6], x[m*8+7], 1);
                *(uint4*)(st + (12 + m) * 4) = u;
            }
        } else {
            // stage final row (fp32) into A region (row-private rewrite)
#pragma unroll 8
            for (int c = 0; c < 96; c++) Astgf[r * 148 + c] = x[c];
        }
    }
    __syncthreads();

    // ---- coalesced global stores -------------------------------------------
    if (mode <= 1) {
        uint4* Eo = (uint4*)(g_ext + rowbase * KEXT);
        for (int n = tid; n < 4608; n += 256) {
            const int r = n / 36, m = n - r * 36;
            Eo[n] = *(uint4*)(Astgu + r * 148 + m * 4);
        }
        if (mode == 0) {
            float* Xo = g_X + rowbase * 96;
            for (int n = tid; n < 3072; n += 256) {
                const int r = n / 24, c4 = n - r * 24;
                *(float4*)(Xo + n * 4) = *(float4*)(Cstg + r * CSTG_STRIDE + c4 * 4);
            }
        }
    } else {
        // scatter to final output: window-reverse + unshift folded in
        for (int n = tid; n < 3072; n += 256) {
            const int r = n / 24, c4 = n - r * 24;
            const long rw = rowbase + r;
            const int w = (int)(rw >> 6), p = (int)(rw & 63);
            const int b = w >> 10, wy = (w >> 5) & 31, wx = w & 31;
            const int ys = (wy * 8 + (p >> 3) + 4) & 255;
            const int xs = (wx * 8 + (p & 7) + 4) & 255;
            *(float4*)(outp + (size_t)((b * 256 + ys) * 256 + xs) * 96 + c4 * 4)
                = *(float4*)(Astgf + r * 148 + c4 * 4);
        }
    }
}

// ---------------------------------------------------------------------------
extern "C" void kernel_launch(void* const* d_in, const int* in_sizes, int n_in,
                              void* d_out, int out_size)
{
    const float* q   = (const float*)d_in[0];
    const float* k   = (const float*)d_in[1];
    const float* v   = (const float*)d_in[2];
    const float* rpb = (const float*)d_in[3];
    const float* ng  = (const float*)d_in[4];
    const float* nb  = (const float*)d_in[5];
    const float* pw  = (const float*)d_in[6];
    const float* pb  = (const float*)d_in[7];
    const float* n2g = (const float*)d_in[8];
    const float* n2b = (const float*)d_in[9];
    const float* w1  = (const float*)d_in[10];
    const float* b1  = (const float*)d_in[11];
    const float* w2  = (const float*)d_in[12];
    const float* b2  = (const float*)d_in[13];
    float* out = (float*)d_out;

    cudaFuncSetAttribute(attn_kernel,
                         cudaFuncAttributeMaxDynamicSharedMemorySize, A_SMEM_FLOATS * 4);
    cudaFuncSetAttribute(gemm_ext_kernel,
                         cudaFuncAttributeMaxDynamicSharedMemorySize, SM_TOTAL);

    prep_wext<<<96, 96>>>(pw, w1, w2);
    attn_kernel<<<8192, 384, A_SMEM_FLOATS * 4>>>(q, k, v, rpb, ng, nb);
    gemm_ext_kernel<<<4096, 256, SM_TOTAL>>>(0, 0, pb, n2g, n2b, nullptr); // proj + LN2
    gemm_ext_kernel<<<4096, 256, SM_TOTAL>>>(1, 1, b1, nullptr, nullptr, nullptr); // fc1 + gelu
    gemm_ext_kernel<<<4096, 256, SM_TOTAL>>>(2, 2, b2, nullptr, nullptr, out);     // fc2 + res
}

// round 9
// speedup vs baseline: 2.1399x; 1.7961x over previous
#include <cuda_runtime.h>
#include <cuda_bf16.h>
#include <cstdint>
#include <math.h>

// ---------------------------------------------------------------------------
// BlindSpotBlock: B=8 H=256 W=256 C=96, WS=8 SS=4 NH=6 CH=16
// attention: SIMT -> ext rows.  proj/LN2/fc1/GELU/fc2/residual: ONE fused
// HMMA kernel (bf16x3 split GEMM, fp32-accurate), zero intermediate DRAM.
// ---------------------------------------------------------------------------

#define NROWS 524288              // B*NW*64 window-linear rows
#define KEXT  288                 // 96(hi) | 96(lo) | 96(hi)
#define NSTEP 18

__device__ __nv_bfloat16 g_ext[(size_t)NROWS * KEXT];   // attention output ext rows
__device__ __nv_bfloat16 g_Wext[3][96 * KEXT];          // W_ext per matrix

typedef unsigned long long u64;

__device__ __forceinline__ uint32_t smem_u32(const void* p){
    uint32_t a;
    asm("{ .reg .u64 t; cvta.to.shared.u64 t, %1; cvt.u32.u64 %0, t; }" : "=r"(a) : "l"(p));
    return a;
}
__device__ __forceinline__ uint4 ldmat4(uint32_t a){
    uint4 r;
    asm volatile("ldmatrix.sync.aligned.m8n8.x4.shared.b16 {%0,%1,%2,%3}, [%4];"
                 : "=r"(r.x), "=r"(r.y), "=r"(r.z), "=r"(r.w) : "r"(a));
    return r;
}
__device__ __forceinline__ void mma_bf16(float* d, const uint4 a, uint32_t b0, uint32_t b1){
    asm volatile("mma.sync.aligned.m16n8k16.row.col.f32.bf16.bf16.f32 "
                 "{%0,%1,%2,%3}, {%4,%5,%6,%7}, {%8,%9}, {%0,%1,%2,%3};"
                 : "+f"(d[0]), "+f"(d[1]), "+f"(d[2]), "+f"(d[3])
                 : "r"(a.x), "r"(a.y), "r"(a.z), "r"(a.w), "r"(b0), "r"(b1));
}
__device__ __forceinline__ unsigned bfpack(float a, float b, int lo){
    __nv_bfloat16 ha = __float2bfloat16(a), hb = __float2bfloat16(b);
    if (lo) {
        ha = __float2bfloat16(a - __bfloat162float(ha));
        hb = __float2bfloat16(b - __bfloat162float(hb));
    }
    return (unsigned)__bfloat16_as_ushort(ha) | ((unsigned)__bfloat16_as_ushort(hb) << 16);
}

// ---------------- prep: build W_ext = [Wh | Wh | Wl] -----------------------
__global__ void prep_wext(const float* __restrict__ pw,
                          const float* __restrict__ w1,
                          const float* __restrict__ w2)
{
    const int c = blockIdx.x, k = threadIdx.x;
    const float* src[3] = {pw, w1, w2};
#pragma unroll
    for (int m = 0; m < 3; m++) {
        const float wv = src[m][c * 96 + k];
        __nv_bfloat16 bh = __float2bfloat16(wv);
        __nv_bfloat16 bl = __float2bfloat16(wv - __bfloat162float(bh));
        g_Wext[m][c * KEXT + k]       = bh;
        g_Wext[m][c * KEXT + 96 + k]  = bh;
        g_Wext[m][c * KEXT + 192 + k] = bl;
    }
}

// ---------------- Kernel A: attention + LN1 -> g_ext (window-linear) -------
#define A_SMEM_FLOATS 19974
__global__ void __launch_bounds__(384, 2)
attn_kernel(const float* __restrict__ q_in,
            const float* __restrict__ k_in,
            const float* __restrict__ v_in,
            const float* __restrict__ rpb,
            const float* __restrict__ ng,
            const float* __restrict__ nb)
{
    extern __shared__ float sm[];
    float* k_s    = sm;
    float* v_s    = sm + 6144;
    float* out_s  = sm + 12288;      // 64 x 97
    float* rpb_s  = sm + 18496;
    int*   base_s = (int*)(sm + 19846);
    int*   reg_s  = (int*)(sm + 19910);

    const int tid  = threadIdx.x;
    const int w    = blockIdx.x;
    const int b    = w >> 10;
    const int widx = w & 1023;
    const int wy   = widx >> 5;
    const int wx   = widx & 31;

    if (tid < 64) {
        const int py = tid >> 3, px = tid & 7;
        const int ys = (wy * 8 + py + 4) & 255;
        const int xs = (wx * 8 + px + 4) & 255;
        base_s[tid] = ((b * 256 + ys) * 256 + xs) * 96;
        const int row = wy * 8 + py, col = wx * 8 + px;
        const int rr = (row < 248) ? 0 : ((row < 252) ? 1 : 2);
        const int cr = (col < 248) ? 0 : ((col < 252) ? 1 : 2);
        reg_s[tid] = rr * 3 + cr;
    }
    for (int n = tid; n < 1350; n += 384) rpb_s[n] = rpb[n];
    __syncthreads();

    for (int n = tid; n < 1536; n += 384) {
        const int p = n / 24, c4 = n - p * 24;
        const int g = base_s[p] + c4 * 4;
        *(float4*)(k_s + p * 96 + c4 * 4) = *(const float4*)(k_in + g);
        *(float4*)(v_s + p * 96 + c4 * 4) = *(const float4*)(v_in + g);
    }
    __syncthreads();

    const int hh = tid >> 6;
    const int i  = tid & 63;
    const int co = hh * 16;
    const int yi = i >> 3, xi = i & 7;
    const int ri = reg_s[i];
    const int myoff = (112 + yi * 15 + xi) * 6 + hh;

    float qv[16];
    {
        const float4* qp = (const float4*)(q_in + base_s[i] + co);
        float4 a = qp[0], bq = qp[1], c = qp[2], d = qp[3];
        qv[0]=a.x*0.25f; qv[1]=a.y*0.25f; qv[2]=a.z*0.25f; qv[3]=a.w*0.25f;
        qv[4]=bq.x*0.25f; qv[5]=bq.y*0.25f; qv[6]=bq.z*0.25f; qv[7]=bq.w*0.25f;
        qv[8]=c.x*0.25f; qv[9]=c.y*0.25f; qv[10]=c.z*0.25f; qv[11]=c.w*0.25f;
        qv[12]=d.x*0.25f; qv[13]=d.y*0.25f; qv[14]=d.z*0.25f; qv[15]=d.w*0.25f;
    }

    float acc[16];
#pragma unroll
    for (int c = 0; c < 16; c++) acc[c] = 0.f;
    float ssum = 0.f;

#pragma unroll 4
    for (int j = 0; j < 64; j++) {
        const float4* kp = (const float4*)(k_s + j * 96 + co);
        float4 k0 = kp[0], k1 = kp[1], k2 = kp[2], k3 = kp[3];
        float s0 = fmaf(qv[0], k0.x, fmaf(qv[1], k0.y, fmaf(qv[2], k0.z, qv[3] * k0.w)));
        float s1 = fmaf(qv[4], k1.x, fmaf(qv[5], k1.y, fmaf(qv[6], k1.z, qv[7] * k1.w)));
        float s2 = fmaf(qv[8], k2.x, fmaf(qv[9], k2.y, fmaf(qv[10], k2.z, qv[11] * k2.w)));
        float s3 = fmaf(qv[12], k3.x, fmaf(qv[13], k3.y, fmaf(qv[14], k3.z, qv[15] * k3.w)));
        float s = (s0 + s1) + (s2 + s3);
        s += rpb_s[myoff - ((j >> 3) * 15 + (j & 7)) * 6];
        const float p = ((j != i) && (reg_s[j] == ri)) ? __expf(s) : 0.f;
        ssum += p;
        const float4* vp = (const float4*)(v_s + j * 96 + co);
        float4 v0 = vp[0], v1 = vp[1], v2 = vp[2], v3 = vp[3];
        acc[0]=fmaf(p,v0.x,acc[0]); acc[1]=fmaf(p,v0.y,acc[1]); acc[2]=fmaf(p,v0.z,acc[2]); acc[3]=fmaf(p,v0.w,acc[3]);
        acc[4]=fmaf(p,v1.x,acc[4]); acc[5]=fmaf(p,v1.y,acc[5]); acc[6]=fmaf(p,v1.z,acc[6]); acc[7]=fmaf(p,v1.w,acc[7]);
        acc[8]=fmaf(p,v2.x,acc[8]); acc[9]=fmaf(p,v2.y,acc[9]); acc[10]=fmaf(p,v2.z,acc[10]); acc[11]=fmaf(p,v2.w,acc[11]);
        acc[12]=fmaf(p,v3.x,acc[12]); acc[13]=fmaf(p,v3.y,acc[13]); acc[14]=fmaf(p,v3.z,acc[14]); acc[15]=fmaf(p,v3.w,acc[15]);
    }

    const float inv = 1.0f / ssum;
#pragma unroll
    for (int c = 0; c < 16; c++)
        out_s[i * 97 + co + c] = fmaf(acc[c], inv, qv[c]);
    __syncthreads();

    if (tid < 64) {
        float* r = out_s + tid * 97;
        float s1 = 0.f, s2 = 0.f;
#pragma unroll 8
        for (int c = 0; c < 96; c++) { const float x = r[c]; s1 += x; s2 = fmaf(x, x, s2); }
        const float mu = s1 * (1.0f / 96.0f);
        const float var = s2 * (1.0f / 96.0f) - mu * mu;
        const float rs = rsqrtf(var + 1e-5f);
#pragma unroll 8
        for (int c = 0; c < 96; c++)
            r[c] = (r[c] - mu) * rs * ng[c] + nb[c];
    }
    __syncthreads();

    uint4* dst = (uint4*)(g_ext + (size_t)w * 64 * KEXT);
    for (int n = tid; n < 2304; n += 384) {
        const int p = n / 36, m = n - p * 36;
        const int blk = (m >= 12 && m < 24) ? 1 : 0;
        const int cb = (m % 12) * 8;
        const float* r = out_s + p * 97 + cb;
        uint4 u;
        u.x = bfpack(r[0], r[1], blk);
        u.y = bfpack(r[2], r[3], blk);
        u.z = bfpack(r[4], r[5], blk);
        u.w = bfpack(r[6], r[7], blk);
        dst[n] = u;
    }
}

// ---------------- fused MLP: proj+LN2+fc1+GELU+fc2+residual+scatter --------
// smem: A ext tile [0, 75776), W tile [75776, 132608), params [132608, 134528)
#define STRIDE_B 592
#define SM_A   0
#define SM_W   75776
#define SM_P   132608
#define SM_TOTAL 134528
#define CSTG_STRIDE 100

__global__ void __launch_bounds__(256, 1)
fused_mlp_kernel(const float* __restrict__ pb,
                 const float* __restrict__ n2g, const float* __restrict__ n2b,
                 const float* __restrict__ b1,  const float* __restrict__ b2,
                 float* __restrict__ outp)
{
    extern __shared__ char smem[];
    const uint32_t sbase = smem_u32(smem);
    const int tid  = threadIdx.x;
    const int wid  = tid >> 5, lane = tid & 31;
    const long rowbase = (long)blockIdx.x * 128;

    float* P = (float*)(smem + SM_P);   // pb | n2g | n2b | b1 | b2 (96 each)
    if (tid < 96) {
        P[tid] = pb[tid];  P[96 + tid] = n2g[tid]; P[192 + tid] = n2b[tid];
        P[288 + tid] = b1[tid]; P[384 + tid] = b2[tid];
    }

    // load A ext tile + W0
    {
        const uint4* Ag = (const uint4*)(g_ext + rowbase * KEXT);
        for (int n = tid; n < 4608; n += 256) {
            const int r = n / 36, m = n - r * 36;
            *(uint4*)(smem + SM_A + r * STRIDE_B + m * 16) = Ag[n];
        }
        const uint4* Wg = (const uint4*)(&g_Wext[0][0]);
        for (int n = tid; n < 3456; n += 256) {
            const int r = n / 36, m = n - r * 36;
            *(uint4*)(smem + SM_W + r * STRIDE_B + m * 16) = Wg[n];
        }
    }
    __syncthreads();

    // fragment geometry
    const int m0  = wid * 16;
    const int g   = lane >> 2;          // row in group
    const int tig = lane & 3;           // col pair
    const uint32_t aBase = sbase + SM_A + (uint32_t)(m0 + (lane & 15)) * STRIDE_B
                         + (uint32_t)(lane >> 4) * 16;
    const int jj = lane >> 3;
    const uint32_t bBase = sbase + SM_W
                         + (uint32_t)(((jj >> 1) * 8) + (lane & 7)) * STRIDE_B
                         + (uint32_t)(jj & 1) * 16;

    float accf[12][4];
    float Xf[12][4];                    // residual fragments

#define MAINLOOP()                                                        \
    {                                                                     \
        _Pragma("unroll")                                                 \
        for (int t = 0; t < 12; t++)                                      \
            { accf[t][0]=0.f; accf[t][1]=0.f; accf[t][2]=0.f; accf[t][3]=0.f; } \
        _Pragma("unroll 2")                                               \
        for (int ks = 0; ks < NSTEP; ks++) {                              \
            const uint4 a = ldmat4(aBase + ks * 32);                      \
            _Pragma("unroll")                                             \
            for (int nt = 0; nt < 6; nt++) {                              \
                const uint4 bf = ldmat4(bBase + nt * (16 * STRIDE_B) + ks * 32); \
                mma_bf16(accf[2 * nt    ], a, bf.x, bf.y);                \
                mma_bf16(accf[2 * nt + 1], a, bf.z, bf.w);                \
            }                                                             \
        }                                                                 \
    }

    // helper: write ext rows (hi|lo|hi) for this thread's two rows
#define WRITE_EXT(vals)                                                   \
    {                                                                     \
        char* rp0 = smem + SM_A + (m0 + g    ) * STRIDE_B;                \
        char* rp1 = smem + SM_A + (m0 + g + 8) * STRIDE_B;                \
        _Pragma("unroll")                                                 \
        for (int t = 0; t < 12; t++) {                                    \
            const int cb = (t * 8 + tig * 2) * 2;                         \
            unsigned h0 = bfpack(vals[t][0], vals[t][1], 0);              \
            unsigned l0 = bfpack(vals[t][0], vals[t][1], 1);              \
            unsigned h1 = bfpack(vals[t][2], vals[t][3], 0);              \
            unsigned l1 = bfpack(vals[t][2], vals[t][3], 1);              \
            *(unsigned*)(rp0 + cb) = h0;                                  \
            *(unsigned*)(rp0 + 192 + cb) = l0;                            \
            *(unsigned*)(rp0 + 384 + cb) = h0;                            \
            *(unsigned*)(rp1 + cb) = h1;                                  \
            *(unsigned*)(rp1 + 192 + cb) = l1;                            \
            *(unsigned*)(rp1 + 384 + cb) = h1;                            \
        }                                                                 \
    }

    // ---------------- stage 1: proj + LN2 ----------------------------------
    MAINLOOP();
    __syncthreads();                    // done reading W0 / A
    {
        // X = C + pb; keep as residual fragments
        float s1a=0.f, s2a=0.f, s1b=0.f, s2b=0.f;
#pragma unroll
        for (int t = 0; t < 12; t++) {
            const int c0 = t * 8 + tig * 2;
            const float bb0 = P[c0], bb1 = P[c0 + 1];
            Xf[t][0] = accf[t][0] + bb0; Xf[t][1] = accf[t][1] + bb1;
            Xf[t][2] = accf[t][2] + bb0; Xf[t][3] = accf[t][3] + bb1;
            s1a += Xf[t][0] + Xf[t][1];
            s2a += Xf[t][0]*Xf[t][0] + Xf[t][1]*Xf[t][1];
            s1b += Xf[t][2] + Xf[t][3];
            s2b += Xf[t][2]*Xf[t][2] + Xf[t][3]*Xf[t][3];
        }
#pragma unroll
        for (int msk = 1; msk <= 2; msk <<= 1) {
            s1a += __shfl_xor_sync(0xFFFFFFFF, s1a, msk);
            s2a += __shfl_xor_sync(0xFFFFFFFF, s2a, msk);
            s1b += __shfl_xor_sync(0xFFFFFFFF, s1b, msk);
            s2b += __shfl_xor_sync(0xFFFFFFFF, s2b, msk);
        }
        const float mua = s1a * (1.0f/96.0f), mub = s1b * (1.0f/96.0f);
        const float rsa = rsqrtf(s2a * (1.0f/96.0f) - mua*mua + 1e-5f);
        const float rsb = rsqrtf(s2b * (1.0f/96.0f) - mub*mub + 1e-5f);
        float nrm[12][4];
#pragma unroll
        for (int t = 0; t < 12; t++) {
            const int c0 = t * 8 + tig * 2;
            const float g0 = P[96 + c0], g1 = P[96 + c0 + 1];
            const float e0 = P[192 + c0], e1 = P[192 + c0 + 1];
            nrm[t][0] = (Xf[t][0] - mua) * rsa * g0 + e0;
            nrm[t][1] = (Xf[t][1] - mua) * rsa * g1 + e1;
            nrm[t][2] = (Xf[t][2] - mub) * rsb * g0 + e0;
            nrm[t][3] = (Xf[t][3] - mub) * rsb * g1 + e1;
        }
        WRITE_EXT(nrm);
    }
    // load W1
    {
        const uint4* Wg = (const uint4*)(&g_Wext[1][0]);
        for (int n = tid; n < 3456; n += 256) {
            const int r = n / 36, m = n - r * 36;
            *(uint4*)(smem + SM_W + r * STRIDE_B + m * 16) = Wg[n];
        }
    }
    __syncthreads();

    // ---------------- stage 2: fc1 + GELU -----------------------------------
    MAINLOOP();
    __syncthreads();
    {
        float hv[12][4];
#pragma unroll
        for (int t = 0; t < 12; t++) {
            const int c0 = t * 8 + tig * 2;
            const float bb0 = P[288 + c0], bb1 = P[288 + c0 + 1];
            float v0 = accf[t][0] + bb0, v1 = accf[t][1] + bb1;
            float v2 = accf[t][2] + bb0, v3 = accf[t][3] + bb1;
            hv[t][0] = 0.5f * v0 * (1.0f + erff(v0 * 0.70710678118654752440f));
            hv[t][1] = 0.5f * v1 * (1.0f + erff(v1 * 0.70710678118654752440f));
            hv[t][2] = 0.5f * v2 * (1.0f + erff(v2 * 0.70710678118654752440f));
            hv[t][3] = 0.5f * v3 * (1.0f + erff(v3 * 0.70710678118654752440f));
        }
        WRITE_EXT(hv);
    }
    // load W2
    {
        const uint4* Wg = (const uint4*)(&g_Wext[2][0]);
        for (int n = tid; n < 3456; n += 256) {
            const int r = n / 36, m = n - r * 36;
            *(uint4*)(smem + SM_W + r * STRIDE_B + m * 16) = Wg[n];
        }
    }
    __syncthreads();

    // ---------------- stage 3: fc2 + residual --------------------------------
    MAINLOOP();
    __syncthreads();                    // done reading W region -> reuse as Cstg
    {
        float* Cstg = (float*)(smem + SM_W);
#pragma unroll
        for (int t = 0; t < 12; t++) {
            const int c0 = t * 8 + tig * 2;
            const float bb0 = P[384 + c0], bb1 = P[384 + c0 + 1];
            *(float2*)(Cstg + (m0 + g    ) * CSTG_STRIDE + c0)
                = make_float2(accf[t][0] + bb0 + Xf[t][0], accf[t][1] + bb1 + Xf[t][1]);
            *(float2*)(Cstg + (m0 + g + 8) * CSTG_STRIDE + c0)
                = make_float2(accf[t][2] + bb0 + Xf[t][2], accf[t][3] + bb1 + Xf[t][3]);
        }
        __syncthreads();
        // coalesced scatter: window-reverse + unshift folded in
        for (int n = tid; n < 3072; n += 256) {
            const int r = n / 24, c4 = n - r * 24;
            const long rw = rowbase + r;
            const int w = (int)(rw >> 6), p = (int)(rw & 63);
            const int b = w >> 10, wy = (w >> 5) & 31, wx = w & 31;
            const int ys = (wy * 8 + (p >> 3) + 4) & 255;
            const int xs = (wx * 8 + (p & 7) + 4) & 255;
            *(float4*)(outp + (size_t)((b * 256 + ys) * 256 + xs) * 96 + c4 * 4)
                = *(float4*)(Cstg + r * CSTG_STRIDE + c4 * 4);
        }
    }
}

// ---------------------------------------------------------------------------
extern "C" void kernel_launch(void* const* d_in, const int* in_sizes, int n_in,
                              void* d_out, int out_size)
{
    const float* q   = (const float*)d_in[0];
    const float* k   = (const float*)d_in[1];
    const float* v   = (const float*)d_in[2];
    const float* rpb = (const float*)d_in[3];
    const float* ng  = (const float*)d_in[4];
    const float* nb  = (const float*)d_in[5];
    const float* pw  = (const float*)d_in[6];
    const float* pb  = (const float*)d_in[7];
    const float* n2g = (const float*)d_in[8];
    const float* n2b = (const float*)d_in[9];
    const float* w1  = (const float*)d_in[10];
    const float* b1  = (const float*)d_in[11];
    const float* w2  = (const float*)d_in[12];
    const float* b2  = (const float*)d_in[13];
    float* out = (float*)d_out;

    cudaFuncSetAttribute(attn_kernel,
                         cudaFuncAttributeMaxDynamicSharedMemorySize, A_SMEM_FLOATS * 4);
    cudaFuncSetAttribute(fused_mlp_kernel,
                         cudaFuncAttributeMaxDynamicSharedMemorySize, SM_TOTAL);

    prep_wext<<<96, 96>>>(pw, w1, w2);
    attn_kernel<<<8192, 384, A_SMEM_FLOATS * 4>>>(q, k, v, rpb, ng, nb);
    fused_mlp_kernel<<<4096, 256, SM_TOTAL>>>(pb, n2g, n2b, b1, b2, out);
}

// round 11
// speedup vs baseline: 2.2166x; 1.0359x over previous
#include <cuda_runtime.h>
#include <cuda_bf16.h>
#include <cstdint>
#include <math.h>

// ---------------------------------------------------------------------------
// BlindSpotBlock: B=8 H=256 W=256 C=96, WS=8 SS=4 NH=6 CH=16
// attention: SIMT (2 queries/thread) -> ext rows.
// proj/LN2/fc1/GELU/fc2/residual: ONE fused HMMA kernel (bf16x3 split GEMM),
// 64-row tiles, 2 CTAs/SM.
// ---------------------------------------------------------------------------

#define NROWS 524288              // B*NW*64 window-linear rows
#define KEXT  288                 // 96(hi) | 96(lo) | 96(hi)
#define NSTEP 18

__device__ __nv_bfloat16 g_ext[(size_t)NROWS * KEXT];   // attention output ext rows
__device__ __nv_bfloat16 g_Wext[3][96 * KEXT];          // W_ext per matrix

__device__ __forceinline__ uint32_t smem_u32(const void* p){
    uint32_t a;
    asm("{ .reg .u64 t; cvta.to.shared.u64 t, %1; cvt.u32.u64 %0, t; }" : "=r"(a) : "l"(p));
    return a;
}
__device__ __forceinline__ uint4 ldmat4(uint32_t a){
    uint4 r;
    asm volatile("ldmatrix.sync.aligned.m8n8.x4.shared.b16 {%0,%1,%2,%3}, [%4];"
                 : "=r"(r.x), "=r"(r.y), "=r"(r.z), "=r"(r.w) : "r"(a));
    return r;
}
__device__ __forceinline__ void mma_bf16(float* d, const uint4 a, uint32_t b0, uint32_t b1){
    asm volatile("mma.sync.aligned.m16n8k16.row.col.f32.bf16.bf16.f32 "
                 "{%0,%1,%2,%3}, {%4,%5,%6,%7}, {%8,%9}, {%0,%1,%2,%3};"
                 : "+f"(d[0]), "+f"(d[1]), "+f"(d[2]), "+f"(d[3])
                 : "r"(a.x), "r"(a.y), "r"(a.z), "r"(a.w), "r"(b0), "r"(b1));
}
__device__ __forceinline__ unsigned bfpack(float a, float b, int lo){
    __nv_bfloat16 ha = __float2bfloat16(a), hb = __float2bfloat16(b);
    if (lo) {
        ha = __float2bfloat16(a - __bfloat162float(ha));
        hb = __float2bfloat16(b - __bfloat162float(hb));
    }
    return (unsigned)__bfloat16_as_ushort(ha) | ((unsigned)__bfloat16_as_ushort(hb) << 16);
}

// ---------------- prep: build W_ext = [Wh | Wh | Wl] -----------------------
__global__ void prep_wext(const float* __restrict__ pw,
                          const float* __restrict__ w1,
                          const float* __restrict__ w2)
{
    const int c = blockIdx.x, k = threadIdx.x;
    const float* src[3] = {pw, w1, w2};
#pragma unroll
    for (int m = 0; m < 3; m++) {
        const float wv = src[m][c * 96 + k];
        __nv_bfloat16 bh = __float2bfloat16(wv);
        __nv_bfloat16 bl = __float2bfloat16(wv - __bfloat162float(bh));
        g_Wext[m][c * KEXT + k]       = bh;
        g_Wext[m][c * KEXT + 96 + k]  = bh;
        g_Wext[m][c * KEXT + 192 + k] = bl;
    }
}

// ---------------- Kernel A: attention + LN1 -> g_ext -----------------------
// 192 threads: thread=(head hh, lane) owns queries lane and lane+32.
#define A_SMEM_FLOATS 19974
__global__ void __launch_bounds__(192, 2)
attn_kernel(const float* __restrict__ q_in,
            const float* __restrict__ k_in,
            const float* __restrict__ v_in,
            const float* __restrict__ rpb,
            const float* __restrict__ ng,
            const float* __restrict__ nb)
{
    extern __shared__ float sm[];
    float* k_s    = sm;
    float* v_s    = sm + 6144;
    float* out_s  = sm + 12288;      // 64 x 97
    float* rpb_s  = sm + 18496;
    int*   base_s = (int*)(sm + 19846);
    int*   reg_s  = (int*)(sm + 19910);

    const int tid  = threadIdx.x;
    const int w    = blockIdx.x;
    const int b    = w >> 10;
    const int widx = w & 1023;
    const int wy   = widx >> 5;
    const int wx   = widx & 31;

    if (tid < 64) {
        const int py = tid >> 3, px = tid & 7;
        const int ys = (wy * 8 + py + 4) & 255;
        const int xs = (wx * 8 + px + 4) & 255;
        base_s[tid] = ((b * 256 + ys) * 256 + xs) * 96;
        const int row = wy * 8 + py, col = wx * 8 + px;
        const int rr = (row < 248) ? 0 : ((row < 252) ? 1 : 2);
        const int cr = (col < 248) ? 0 : ((col < 252) ? 1 : 2);
        reg_s[tid] = rr * 3 + cr;
    }
    for (int n = tid; n < 1350; n += 192) rpb_s[n] = rpb[n];
    __syncthreads();

    for (int n = tid; n < 1536; n += 192) {
        const int p = n / 24, c4 = n - p * 24;
        const int g = base_s[p] + c4 * 4;
        *(float4*)(k_s + p * 96 + c4 * 4) = *(const float4*)(k_in + g);
        *(float4*)(v_s + p * 96 + c4 * 4) = *(const float4*)(v_in + g);
    }
    __syncthreads();

    const int hh   = tid >> 5;       // 0..5 (whole warp same head)
    const int lane = tid & 31;
    const int co   = hh * 16;
    const int i0   = lane, i1 = lane + 32;
    const int ri0  = reg_s[i0], ri1 = reg_s[i1];
    const int myoff0 = (112 + (i0 >> 3) * 15 + (i0 & 7)) * 6 + hh;
    const int myoff1 = (112 + (i1 >> 3) * 15 + (i1 & 7)) * 6 + hh;

    float qv0[16], qv1[16];
    {
        const float4* qp = (const float4*)(q_in + base_s[i0] + co);
        float4 a = qp[0], bq = qp[1], c = qp[2], d = qp[3];
        qv0[0]=a.x*0.25f; qv0[1]=a.y*0.25f; qv0[2]=a.z*0.25f; qv0[3]=a.w*0.25f;
        qv0[4]=bq.x*0.25f; qv0[5]=bq.y*0.25f; qv0[6]=bq.z*0.25f; qv0[7]=bq.w*0.25f;
        qv0[8]=c.x*0.25f; qv0[9]=c.y*0.25f; qv0[10]=c.z*0.25f; qv0[11]=c.w*0.25f;
        qv0[12]=d.x*0.25f; qv0[13]=d.y*0.25f; qv0[14]=d.z*0.25f; qv0[15]=d.w*0.25f;
    }
    {
        const float4* qp = (const float4*)(q_in + base_s[i1] + co);
        float4 a = qp[0], bq = qp[1], c = qp[2], d = qp[3];
        qv1[0]=a.x*0.25f; qv1[1]=a.y*0.25f; qv1[2]=a.z*0.25f; qv1[3]=a.w*0.25f;
        qv1[4]=bq.x*0.25f; qv1[5]=bq.y*0.25f; qv1[6]=bq.z*0.25f; qv1[7]=bq.w*0.25f;
        qv1[8]=c.x*0.25f; qv1[9]=c.y*0.25f; qv1[10]=c.z*0.25f; qv1[11]=c.w*0.25f;
        qv1[12]=d.x*0.25f; qv1[13]=d.y*0.25f; qv1[14]=d.z*0.25f; qv1[15]=d.w*0.25f;
    }

    float acc0[16], acc1[16];
#pragma unroll
    for (int c = 0; c < 16; c++) { acc0[c] = 0.f; acc1[c] = 0.f; }
    float ssum0 = 0.f, ssum1 = 0.f;

#pragma unroll 4
    for (int j = 0; j < 64; j++) {
        const float4* kp = (const float4*)(k_s + j * 96 + co);   // broadcast
        float4 k0 = kp[0], k1 = kp[1], k2 = kp[2], k3 = kp[3];
        float a0 = fmaf(qv0[0], k0.x, fmaf(qv0[1], k0.y, fmaf(qv0[2], k0.z, qv0[3] * k0.w)));
        float a1 = fmaf(qv0[4], k1.x, fmaf(qv0[5], k1.y, fmaf(qv0[6], k1.z, qv0[7] * k1.w)));
        float a2 = fmaf(qv0[8], k2.x, fmaf(qv0[9], k2.y, fmaf(qv0[10], k2.z, qv0[11] * k2.w)));
        float a3 = fmaf(qv0[12], k3.x, fmaf(qv0[13], k3.y, fmaf(qv0[14], k3.z, qv0[15] * k3.w)));
        float b0 = fmaf(qv1[0], k0.x, fmaf(qv1[1], k0.y, fmaf(qv1[2], k0.z, qv1[3] * k0.w)));
        float b1 = fmaf(qv1[4], k1.x, fmaf(qv1[5], k1.y, fmaf(qv1[6], k1.z, qv1[7] * k1.w)));
        float b2 = fmaf(qv1[8], k2.x, fmaf(qv1[9], k2.y, fmaf(qv1[10], k2.z, qv1[11] * k2.w)));
        float b3 = fmaf(qv1[12], k3.x, fmaf(qv1[13], k3.y, fmaf(qv1[14], k3.z, qv1[15] * k3.w)));
        const int joff = ((j >> 3) * 15 + (j & 7)) * 6;
        float s0 = (a0 + a1) + (a2 + a3) + rpb_s[myoff0 - joff];
        float s1 = (b0 + b1) + (b2 + b3) + rpb_s[myoff1 - joff];
        const int rj = reg_s[j];
        const float p0 = ((j != i0) && (rj == ri0)) ? __expf(s0) : 0.f;
        const float p1 = ((j != i1) && (rj == ri1)) ? __expf(s1) : 0.f;
        ssum0 += p0; ssum1 += p1;
        const float4* vp = (const float4*)(v_s + j * 96 + co);   // broadcast
        float4 v0 = vp[0], v1 = vp[1], v2 = vp[2], v3 = vp[3];
        acc0[0]=fmaf(p0,v0.x,acc0[0]); acc0[1]=fmaf(p0,v0.y,acc0[1]); acc0[2]=fmaf(p0,v0.z,acc0[2]); acc0[3]=fmaf(p0,v0.w,acc0[3]);
        acc0[4]=fmaf(p0,v1.x,acc0[4]); acc0[5]=fmaf(p0,v1.y,acc0[5]); acc0[6]=fmaf(p0,v1.z,acc0[6]); acc0[7]=fmaf(p0,v1.w,acc0[7]);
        acc0[8]=fmaf(p0,v2.x,acc0[8]); acc0[9]=fmaf(p0,v2.y,acc0[9]); acc0[10]=fmaf(p0,v2.z,acc0[10]); acc0[11]=fmaf(p0,v2.w,acc0[11]);
        acc0[12]=fmaf(p0,v3.x,acc0[12]); acc0[13]=fmaf(p0,v3.y,acc0[13]); acc0[14]=fmaf(p0,v3.z,acc0[14]); acc0[15]=fmaf(p0,v3.w,acc0[15]);
        acc1[0]=fmaf(p1,v0.x,acc1[0]); acc1[1]=fmaf(p1,v0.y,acc1[1]); acc1[2]=fmaf(p1,v0.z,acc1[2]); acc1[3]=fmaf(p1,v0.w,acc1[3]);
        acc1[4]=fmaf(p1,v1.x,acc1[4]); acc1[5]=fmaf(p1,v1.y,acc1[5]); acc1[6]=fmaf(p1,v1.z,acc1[6]); acc1[7]=fmaf(p1,v1.w,acc1[7]);
        acc1[8]=fmaf(p1,v2.x,acc1[8]); acc1[9]=fmaf(p1,v2.y,acc1[9]); acc1[10]=fmaf(p1,v2.z,acc1[10]); acc1[11]=fmaf(p1,v2.w,acc1[11]);
        acc1[12]=fmaf(p1,v3.x,acc1[12]); acc1[13]=fmaf(p1,v3.y,acc1[13]); acc1[14]=fmaf(p1,v3.z,acc1[14]); acc1[15]=fmaf(p1,v3.w,acc1[15]);
    }

    const float inv0 = 1.0f / ssum0, inv1 = 1.0f / ssum1;
#pragma unroll
    for (int c = 0; c < 16; c++) {
        out_s[i0 * 97 + co + c] = fmaf(acc0[c], inv0, qv0[c]);
        out_s[i1 * 97 + co + c] = fmaf(acc1[c], inv1, qv1[c]);
    }
    __syncthreads();

    // LayerNorm1 (threads 0..63, one row each)
    if (tid < 64) {
        float* r = out_s + tid * 97;
        float s1 = 0.f, s2 = 0.f;
#pragma unroll 8
        for (int c = 0; c < 96; c++) { const float x = r[c]; s1 += x; s2 = fmaf(x, x, s2); }
        const float mu = s1 * (1.0f / 96.0f);
        const float var = s2 * (1.0f / 96.0f) - mu * mu;
        const float rs = rsqrtf(var + 1e-5f);
#pragma unroll 8
        for (int c = 0; c < 96; c++)
            r[c] = (r[c] - mu) * rs * ng[c] + nb[c];
    }
    __syncthreads();

    // write ext rows (hi | lo | hi), coalesced uint4 (36 per row)
    uint4* dst = (uint4*)(g_ext + (size_t)w * 64 * KEXT);
    for (int n = tid; n < 2304; n += 192) {
        const int p = n / 36, m = n - p * 36;
        const int blk = (m >= 12 && m < 24) ? 1 : 0;
        const int cb = (m % 12) * 8;
        const float* r = out_s + p * 97 + cb;
        uint4 u;
        u.x = bfpack(r[0], r[1], blk);
        u.y = bfpack(r[2], r[3], blk);
        u.z = bfpack(r[4], r[5], blk);
        u.w = bfpack(r[6], r[7], blk);
        dst[n] = u;
    }
}

// ---------------- fused MLP: 64-row tiles, 2 CTAs/SM -----------------------
// smem: A ext tile [0, 37888), W tile [37888, 94720), params [94720, 96640)
#define STRIDE_B 592
#define SM_A   0
#define SM_W   37888
#define SM_P   94720
#define SM_TOTAL 96640
#define CSTG_STRIDE 100

__global__ void __launch_bounds__(128, 2)
fused_mlp_kernel(const float* __restrict__ pb,
                 const float* __restrict__ n2g, const float* __restrict__ n2b,
                 const float* __restrict__ b1,  const float* __restrict__ b2,
                 float* __restrict__ outp)
{
    extern __shared__ char smem[];
    const uint32_t sbase = smem_u32(smem);
    const int tid  = threadIdx.x;
    const int wid  = tid >> 5, lane = tid & 31;
    const long rowbase = (long)blockIdx.x * 64;

    float* P = (float*)(smem + SM_P);   // pb | n2g | n2b | b1 | b2
    if (tid < 96) {
        P[tid] = pb[tid];  P[96 + tid] = n2g[tid]; P[192 + tid] = n2b[tid];
        P[288 + tid] = b1[tid]; P[384 + tid] = b2[tid];
    }

    // load A ext tile (64 x 288) + W0 (96 x 288)
    {
        const uint4* Ag = (const uint4*)(g_ext + rowbase * KEXT);
        for (int n = tid; n < 2304; n += 128) {
            const int r = n / 36, m = n - r * 36;
            *(uint4*)(smem + SM_A + r * STRIDE_B + m * 16) = Ag[n];
        }
        const uint4* Wg = (const uint4*)(&g_Wext[0][0]);
        for (int n = tid; n < 3456; n += 128) {
            const int r = n / 36, m = n - r * 36;
            *(uint4*)(smem + SM_W + r * STRIDE_B + m * 16) = Wg[n];
        }
    }
    __syncthreads();

    const int m0  = wid * 16;
    const int g   = lane >> 2;
    const int tig = lane & 3;
    const uint32_t aBase = sbase + SM_A + (uint32_t)(m0 + (lane & 15)) * STRIDE_B
                         + (uint32_t)(lane >> 4) * 16;
    const int jj = lane >> 3;
    const uint32_t bBase = sbase + SM_W
                         + (uint32_t)(((jj >> 1) * 8) + (lane & 7)) * STRIDE_B
                         + (uint32_t)(jj & 1) * 16;

    float accf[12][4];
    float Xf[12][4];

#define MAINLOOP()                                                        \
    {                                                                     \
        _Pragma("unroll")                                                 \
        for (int t = 0; t < 12; t++)                                      \
            { accf[t][0]=0.f; accf[t][1]=0.f; accf[t][2]=0.f; accf[t][3]=0.f; } \
        _Pragma("unroll 2")                                               \
        for (int ks = 0; ks < NSTEP; ks++) {                              \
            const uint4 a = ldmat4(aBase + ks * 32);                      \
            _Pragma("unroll")                                             \
            for (int nt = 0; nt < 6; nt++) {                              \
                const uint4 bf = ldmat4(bBase + nt * (16 * STRIDE_B) + ks * 32); \
                mma_bf16(accf[2 * nt    ], a, bf.x, bf.y);                \
                mma_bf16(accf[2 * nt + 1], a, bf.z, bf.w);                \
            }                                                             \
        }                                                                 \
    }

#define WRITE_EXT(vals)                                                   \
    {                                                                     \
        char* rp0 = smem + SM_A + (m0 + g    ) * STRIDE_B;                \
        char* rp1 = smem + SM_A + (m0 + g + 8) * STRIDE_B;                \
        _Pragma("unroll")                                                 \
        for (int t = 0; t < 12; t++) {                                    \
            const int cb = (t * 8 + tig * 2) * 2;                         \
            unsigned h0 = bfpack(vals[t][0], vals[t][1], 0);              \
            unsigned l0 = bfpack(vals[t][0], vals[t][1], 1);              \
            unsigned h1 = bfpack(vals[t][2], vals[t][3], 0);              \
            unsigned l1 = bfpack(vals[t][2], vals[t][3], 1);              \
            *(unsigned*)(rp0 + cb) = h0;                                  \
            *(unsigned*)(rp0 + 192 + cb) = l0;                            \
            *(unsigned*)(rp0 + 384 + cb) = h0;                            \
            *(unsigned*)(rp1 + cb) = h1;                                  \
            *(unsigned*)(rp1 + 192 + cb) = l1;                            \
            *(unsigned*)(rp1 + 384 + cb) = h1;                            \
        }                                                                 \
    }

    // ---------------- stage 1: proj + LN2 ----------------------------------
    MAINLOOP();
    __syncthreads();
    {
        float s1a=0.f, s2a=0.f, s1b=0.f, s2b=0.f;
#pragma unroll
        for (int t = 0; t < 12; t++) {
            const int c0 = t * 8 + tig * 2;
            const float bb0 = P[c0], bb1 = P[c0 + 1];
            Xf[t][0] = accf[t][0] + bb0; Xf[t][1] = accf[t][1] + bb1;
            Xf[t][2] = accf[t][2] + bb0; Xf[t][3] = accf[t][3] + bb1;
            s1a += Xf[t][0] + Xf[t][1];
            s2a += Xf[t][0]*Xf[t][0] + Xf[t][1]*Xf[t][1];
            s1b += Xf[t][2] + Xf[t][3];
            s2b += Xf[t][2]*Xf[t][2] + Xf[t][3]*Xf[t][3];
        }
#pragma unroll
        for (int msk = 1; msk <= 2; msk <<= 1) {
            s1a += __shfl_xor_sync(0xFFFFFFFF, s1a, msk);
            s2a += __shfl_xor_sync(0xFFFFFFFF, s2a, msk);
            s1b += __shfl_xor_sync(0xFFFFFFFF, s1b, msk);
            s2b += __shfl_xor_sync(0xFFFFFFFF, s2b, msk);
        }
        const float mua = s1a * (1.0f/96.0f), mub = s1b * (1.0f/96.0f);
        const float rsa = rsqrtf(s2a * (1.0f/96.0f) - mua*mua + 1e-5f);
        const float rsb = rsqrtf(s2b * (1.0f/96.0f) - mub*mub + 1e-5f);
        float nrm[12][4];
#pragma unroll
        for (int t = 0; t < 12; t++) {
            const int c0 = t * 8 + tig * 2;
            const float g0 = P[96 + c0], g1 = P[96 + c0 + 1];
            const float e0 = P[192 + c0], e1 = P[192 + c0 + 1];
            nrm[t][0] = (Xf[t][0] - mua) * rsa * g0 + e0;
            nrm[t][1] = (Xf[t][1] - mua) * rsa * g1 + e1;
            nrm[t][2] = (Xf[t][2] - mub) * rsb * g0 + e0;
            nrm[t][3] = (Xf[t][3] - mub) * rsb * g1 + e1;
        }
        WRITE_EXT(nrm);
    }
    {
        const uint4* Wg = (const uint4*)(&g_Wext[1][0]);
        for (int n = tid; n < 3456; n += 128) {
            const int r = n / 36, m = n - r * 36;
            *(uint4*)(smem + SM_W + r * STRIDE_B + m * 16) = Wg[n];
        }
    }
    __syncthreads();

    // ---------------- stage 2: fc1 + GELU -----------------------------------
    MAINLOOP();
    __syncthreads();
    {
        float hv[12][4];
#pragma unroll
        for (int t = 0; t < 12; t++) {
            const int c0 = t * 8 + tig * 2;
            const float bb0 = P[288 + c0], bb1 = P[288 + c0 + 1];
            float v0 = accf[t][0] + bb0, v1 = accf[t][1] + bb1;
            float v2 = accf[t][2] + bb0, v3 = accf[t][3] + bb1;
            hv[t][0] = 0.5f * v0 * (1.0f + erff(v0 * 0.70710678118654752440f));
            hv[t][1] = 0.5f * v1 * (1.0f + erff(v1 * 0.70710678118654752440f));
            hv[t][2] = 0.5f * v2 * (1.0f + erff(v2 * 0.70710678118654752440f));
            hv[t][3] = 0.5f * v3 * (1.0f + erff(v3 * 0.70710678118654752440f));
        }
        WRITE_EXT(hv);
    }
    {
        const uint4* Wg = (const uint4*)(&g_Wext[2][0]);
        for (int n = tid; n < 3456; n += 128) {
            const int r = n / 36, m = n - r * 36;
            *(uint4*)(smem + SM_W + r * STRIDE_B + m * 16) = Wg[n];
        }
    }
    __syncthreads();

    // ---------------- stage 3: fc2 + residual --------------------------------
    MAINLOOP();
    __syncthreads();
    {
        float* Cstg = (float*)(smem + SM_W);
#pragma unroll
        for (int t = 0; t < 12; t++) {
            const int c0 = t * 8 + tig * 2;
            const float bb0 = P[384 + c0], bb1 = P[384 + c0 + 1];
            *(float2*)(Cstg + (m0 + g    ) * CSTG_STRIDE + c0)
                = make_float2(accf[t][0] + bb0 + Xf[t][0], accf[t][1] + bb1 + Xf[t][1]);
            *(float2*)(Cstg + (m0 + g + 8) * CSTG_STRIDE + c0)
                = make_float2(accf[t][2] + bb0 + Xf[t][2], accf[t][3] + bb1 + Xf[t][3]);
        }
        __syncthreads();
        for (int n = tid; n < 1536; n += 128) {
            const int r = n / 24, c4 = n - r * 24;
            const long rw = rowbase + r;
            const int w = (int)(rw >> 6), p = (int)(rw & 63);
            const int b = w >> 10, wy = (w >> 5) & 31, wx = w & 31;
            const int ys = (wy * 8 + (p >> 3) + 4) & 255;
            const int xs = (wx * 8 + (p & 7) + 4) & 255;
            *(float4*)(outp + (size_t)((b * 256 + ys) * 256 + xs) * 96 + c4 * 4)
                = *(float4*)(Cstg + r * CSTG_STRIDE + c4 * 4);
        }
    }
}

// ---------------------------------------------------------------------------
extern "C" void kernel_launch(void* const* d_in, const int* in_sizes, int n_in,
                              void* d_out, int out_size)
{
    const float* q   = (const float*)d_in[0];
    const float* k   = (const float*)d_in[1];
    const float* v   = (const float*)d_in[2];
    const float* rpb = (const float*)d_in[3];
    const float* ng  = (const float*)d_in[4];
    const float* nb  = (const float*)d_in[5];
    const float* pw  = (const float*)d_in[6];
    const float* pb  = (const float*)d_in[7];
    const float* n2g = (const float*)d_in[8];
    const float* n2b = (const float*)d_in[9];
    const float* w1  = (const float*)d_in[10];
    const float* b1  = (const float*)d_in[11];
    const float* w2  = (const float*)d_in[12];
    const float* b2  = (const float*)d_in[13];
    float* out = (float*)d_out;

    cudaFuncSetAttribute(attn_kernel,
                         cudaFuncAttributeMaxDynamicSharedMemorySize, A_SMEM_FLOATS * 4);
    cudaFuncSetAttribute(fused_mlp_kernel,
                         cudaFuncAttributeMaxDynamicSharedMemorySize, SM_TOTAL);

    prep_wext<<<96, 96>>>(pw, w1, w2);
    attn_kernel<<<8192, 192, A_SMEM_FLOATS * 4>>>(q, k, v, rpb, ng, nb);
    fused_mlp_kernel<<<8192, 128, SM_TOTAL>>>(pb, n2g, n2b, b1, b2, out);
}

// round 12
// speedup vs baseline: 2.6176x; 1.1809x over previous
#include <cuda_runtime.h>
#include <cuda_bf16.h>
#include <cstdint>
#include <math.h>

// ---------------------------------------------------------------------------
// BlindSpotBlock: B=8 H=256 W=256 C=96, WS=8 SS=4 NH=6 CH=16
// attention: SIMT (2 queries/thread) -> compact ext rows [hi|lo] (192 cols).
// proj/LN2/fc1/GELU/fc2/residual: ONE fused HMMA kernel; bf16x3 split GEMM
// realized by ALIASING the duplicate blocks in smem -> 66KB -> 3 CTAs/SM.
// ---------------------------------------------------------------------------

#define NROWS 524288              // B*NW*64 window-linear rows
#define KEXT  192                 // stored: 96(hi) | 96(lo)
#define NSTEP 18                  // logical K = 288 via aliasing

__device__ __nv_bfloat16 g_ext[(size_t)NROWS * KEXT];   // attention output ext rows
__device__ __nv_bfloat16 g_Wext[3][96 * KEXT];          // [Wh|Wl] per matrix

__device__ __forceinline__ uint32_t smem_u32(const void* p){
    uint32_t a;
    asm("{ .reg .u64 t; cvta.to.shared.u64 t, %1; cvt.u32.u64 %0, t; }" : "=r"(a) : "l"(p));
    return a;
}
__device__ __forceinline__ uint4 ldmat4(uint32_t a){
    uint4 r;
    asm volatile("ldmatrix.sync.aligned.m8n8.x4.shared.b16 {%0,%1,%2,%3}, [%4];"
                 : "=r"(r.x), "=r"(r.y), "=r"(r.z), "=r"(r.w) : "r"(a));
    return r;
}
__device__ __forceinline__ void mma_bf16(float* d, const uint4 a, uint32_t b0, uint32_t b1){
    asm volatile("mma.sync.aligned.m16n8k16.row.col.f32.bf16.bf16.f32 "
                 "{%0,%1,%2,%3}, {%4,%5,%6,%7}, {%8,%9}, {%0,%1,%2,%3};"
                 : "+f"(d[0]), "+f"(d[1]), "+f"(d[2]), "+f"(d[3])
                 : "r"(a.x), "r"(a.y), "r"(a.z), "r"(a.w), "r"(b0), "r"(b1));
}
__device__ __forceinline__ unsigned bfpack(float a, float b, int lo){
    __nv_bfloat16 ha = __float2bfloat16(a), hb = __float2bfloat16(b);
    if (lo) {
        ha = __float2bfloat16(a - __bfloat162float(ha));
        hb = __float2bfloat16(b - __bfloat162float(hb));
    }
    return (unsigned)__bfloat16_as_ushort(ha) | ((unsigned)__bfloat16_as_ushort(hb) << 16);
}

// ---------------- prep: build W_ext = [Wh | Wl] ----------------------------
__global__ void prep_wext(const float* __restrict__ pw,
                          const float* __restrict__ w1,
                          const float* __restrict__ w2)
{
    const int c = blockIdx.x, k = threadIdx.x;
    const float* src[3] = {pw, w1, w2};
#pragma unroll
    for (int m = 0; m < 3; m++) {
        const float wv = src[m][c * 96 + k];
        __nv_bfloat16 bh = __float2bfloat16(wv);
        __nv_bfloat16 bl = __float2bfloat16(wv - __bfloat162float(bh));
        g_Wext[m][c * KEXT + k]      = bh;
        g_Wext[m][c * KEXT + 96 + k] = bl;
    }
}

// ---------------- Kernel A: attention + LN1 -> g_ext -----------------------
// 192 threads: thread=(head hh, lane) owns queries lane and lane+32.
#define A_SMEM_FLOATS 19974
__global__ void __launch_bounds__(192, 2)
attn_kernel(const float* __restrict__ q_in,
            const float* __restrict__ k_in,
            const float* __restrict__ v_in,
            const float* __restrict__ rpb,
            const float* __restrict__ ng,
            const float* __restrict__ nb)
{
    extern __shared__ float sm[];
    float* k_s    = sm;
    float* v_s    = sm + 6144;
    float* out_s  = sm + 12288;      // 64 x 97
    float* rpb_s  = sm + 18496;
    int*   base_s = (int*)(sm + 19846);
    int*   reg_s  = (int*)(sm + 19910);

    const int tid  = threadIdx.x;
    const int w    = blockIdx.x;
    const int b    = w >> 10;
    const int widx = w & 1023;
    const int wy   = widx >> 5;
    const int wx   = widx & 31;

    if (tid < 64) {
        const int py = tid >> 3, px = tid & 7;
        const int ys = (wy * 8 + py + 4) & 255;
        const int xs = (wx * 8 + px + 4) & 255;
        base_s[tid] = ((b * 256 + ys) * 256 + xs) * 96;
        const int row = wy * 8 + py, col = wx * 8 + px;
        const int rr = (row < 248) ? 0 : ((row < 252) ? 1 : 2);
        const int cr = (col < 248) ? 0 : ((col < 252) ? 1 : 2);
        reg_s[tid] = rr * 3 + cr;
    }
    for (int n = tid; n < 1350; n += 192) rpb_s[n] = rpb[n];
    __syncthreads();

    for (int n = tid; n < 1536; n += 192) {
        const int p = n / 24, c4 = n - p * 24;
        const int g = base_s[p] + c4 * 4;
        *(float4*)(k_s + p * 96 + c4 * 4) = *(const float4*)(k_in + g);
        *(float4*)(v_s + p * 96 + c4 * 4) = *(const float4*)(v_in + g);
    }
    __syncthreads();

    const int hh   = tid >> 5;
    const int lane = tid & 31;
    const int co   = hh * 16;
    const int i0   = lane, i1 = lane + 32;
    const int ri0  = reg_s[i0], ri1 = reg_s[i1];
    const int myoff0 = (112 + (i0 >> 3) * 15 + (i0 & 7)) * 6 + hh;
    const int myoff1 = (112 + (i1 >> 3) * 15 + (i1 & 7)) * 6 + hh;

    float qv0[16], qv1[16];
    {
        const float4* qp = (const float4*)(q_in + base_s[i0] + co);
        float4 a = qp[0], bq = qp[1], c = qp[2], d = qp[3];
        qv0[0]=a.x*0.25f; qv0[1]=a.y*0.25f; qv0[2]=a.z*0.25f; qv0[3]=a.w*0.25f;
        qv0[4]=bq.x*0.25f; qv0[5]=bq.y*0.25f; qv0[6]=bq.z*0.25f; qv0[7]=bq.w*0.25f;
        qv0[8]=c.x*0.25f; qv0[9]=c.y*0.25f; qv0[10]=c.z*0.25f; qv0[11]=c.w*0.25f;
        qv0[12]=d.x*0.25f; qv0[13]=d.y*0.25f; qv0[14]=d.z*0.25f; qv0[15]=d.w*0.25f;
    }
    {
        const float4* qp = (const float4*)(q_in + base_s[i1] + co);
        float4 a = qp[0], bq = qp[1], c = qp[2], d = qp[3];
        qv1[0]=a.x*0.25f; qv1[1]=a.y*0.25f; qv1[2]=a.z*0.25f; qv1[3]=a.w*0.25f;
        qv1[4]=bq.x*0.25f; qv1[5]=bq.y*0.25f; qv1[6]=bq.z*0.25f; qv1[7]=bq.w*0.25f;
        qv1[8]=c.x*0.25f; qv1[9]=c.y*0.25f; qv1[10]=c.z*0.25f; qv1[11]=c.w*0.25f;
        qv1[12]=d.x*0.25f; qv1[13]=d.y*0.25f; qv1[14]=d.z*0.25f; qv1[15]=d.w*0.25f;
    }

    float acc0[16], acc1[16];
#pragma unroll
    for (int c = 0; c < 16; c++) { acc0[c] = 0.f; acc1[c] = 0.f; }
    float ssum0 = 0.f, ssum1 = 0.f;

#pragma unroll 4
    for (int j = 0; j < 64; j++) {
        const float4* kp = (const float4*)(k_s + j * 96 + co);
        float4 k0 = kp[0], k1 = kp[1], k2 = kp[2], k3 = kp[3];
        float a0 = fmaf(qv0[0], k0.x, fmaf(qv0[1], k0.y, fmaf(qv0[2], k0.z, qv0[3] * k0.w)));
        float a1 = fmaf(qv0[4], k1.x, fmaf(qv0[5], k1.y, fmaf(qv0[6], k1.z, qv0[7] * k1.w)));
        float a2 = fmaf(qv0[8], k2.x, fmaf(qv0[9], k2.y, fmaf(qv0[10], k2.z, qv0[11] * k2.w)));
        float a3 = fmaf(qv0[12], k3.x, fmaf(qv0[13], k3.y, fmaf(qv0[14], k3.z, qv0[15] * k3.w)));
        float b0 = fmaf(qv1[0], k0.x, fmaf(qv1[1], k0.y, fmaf(qv1[2], k0.z, qv1[3] * k0.w)));
        float b1 = fmaf(qv1[4], k1.x, fmaf(qv1[5], k1.y, fmaf(qv1[6], k1.z, qv1[7] * k1.w)));
        float b2 = fmaf(qv1[8], k2.x, fmaf(qv1[9], k2.y, fmaf(qv1[10], k2.z, qv1[11] * k2.w)));
        float b3 = fmaf(qv1[12], k3.x, fmaf(qv1[13], k3.y, fmaf(qv1[14], k3.z, qv1[15] * k3.w)));
        const int joff = ((j >> 3) * 15 + (j & 7)) * 6;
        float s0 = (a0 + a1) + (a2 + a3) + rpb_s[myoff0 - joff];
        float s1 = (b0 + b1) + (b2 + b3) + rpb_s[myoff1 - joff];
        const int rj = reg_s[j];
        const float p0 = ((j != i0) && (rj == ri0)) ? __expf(s0) : 0.f;
        const float p1 = ((j != i1) && (rj == ri1)) ? __expf(s1) : 0.f;
        ssum0 += p0; ssum1 += p1;
        const float4* vp = (const float4*)(v_s + j * 96 + co);
        float4 v0 = vp[0], v1 = vp[1], v2 = vp[2], v3 = vp[3];
        acc0[0]=fmaf(p0,v0.x,acc0[0]); acc0[1]=fmaf(p0,v0.y,acc0[1]); acc0[2]=fmaf(p0,v0.z,acc0[2]); acc0[3]=fmaf(p0,v0.w,acc0[3]);
        acc0[4]=fmaf(p0,v1.x,acc0[4]); acc0[5]=fmaf(p0,v1.y,acc0[5]); acc0[6]=fmaf(p0,v1.z,acc0[6]); acc0[7]=fmaf(p0,v1.w,acc0[7]);
        acc0[8]=fmaf(p0,v2.x,acc0[8]); acc0[9]=fmaf(p0,v2.y,acc0[9]); acc0[10]=fmaf(p0,v2.z,acc0[10]); acc0[11]=fmaf(p0,v2.w,acc0[11]);
        acc0[12]=fmaf(p0,v3.x,acc0[12]); acc0[13]=fmaf(p0,v3.y,acc0[13]); acc0[14]=fmaf(p0,v3.z,acc0[14]); acc0[15]=fmaf(p0,v3.w,acc0[15]);
        acc1[0]=fmaf(p1,v0.x,acc1[0]); acc1[1]=fmaf(p1,v0.y,acc1[1]); acc1[2]=fmaf(p1,v0.z,acc1[2]); acc1[3]=fmaf(p1,v0.w,acc1[3]);
        acc1[4]=fmaf(p1,v1.x,acc1[4]); acc1[5]=fmaf(p1,v1.y,acc1[5]); acc1[6]=fmaf(p1,v1.z,acc1[6]); acc1[7]=fmaf(p1,v1.w,acc1[7]);
        acc1[8]=fmaf(p1,v2.x,acc1[8]); acc1[9]=fmaf(p1,v2.y,acc1[9]); acc1[10]=fmaf(p1,v2.z,acc1[10]); acc1[11]=fmaf(p1,v2.w,acc1[11]);
        acc1[12]=fmaf(p1,v3.x,acc1[12]); acc1[13]=fmaf(p1,v3.y,acc1[13]); acc1[14]=fmaf(p1,v3.z,acc1[14]); acc1[15]=fmaf(p1,v3.w,acc1[15]);
    }

    const float inv0 = 1.0f / ssum0, inv1 = 1.0f / ssum1;
#pragma unroll
    for (int c = 0; c < 16; c++) {
        out_s[i0 * 97 + co + c] = fmaf(acc0[c], inv0, qv0[c]);
        out_s[i1 * 97 + co + c] = fmaf(acc1[c], inv1, qv1[c]);
    }
    __syncthreads();

    if (tid < 64) {
        float* r = out_s + tid * 97;
        float s1 = 0.f, s2 = 0.f;
#pragma unroll 8
        for (int c = 0; c < 96; c++) { const float x = r[c]; s1 += x; s2 = fmaf(x, x, s2); }
        const float mu = s1 * (1.0f / 96.0f);
        const float var = s2 * (1.0f / 96.0f) - mu * mu;
        const float rs = rsqrtf(var + 1e-5f);
#pragma unroll 8
        for (int c = 0; c < 96; c++)
            r[c] = (r[c] - mu) * rs * ng[c] + nb[c];
    }
    __syncthreads();

    // write compact ext rows (hi | lo), 24 uint4 per row
    uint4* dst = (uint4*)(g_ext + (size_t)w * 64 * KEXT);
    for (int n = tid; n < 1536; n += 192) {
        const int p = n / 24, m = n - p * 24;
        const int blk = (m >= 12) ? 1 : 0;
        const int cb = (m % 12) * 8;
        const float* r = out_s + p * 97 + cb;
        uint4 u;
        u.x = bfpack(r[0], r[1], blk);
        u.y = bfpack(r[2], r[3], blk);
        u.z = bfpack(r[4], r[5], blk);
        u.w = bfpack(r[6], r[7], blk);
        dst[n] = u;
    }
}

// ---------------- fused MLP: compact tiles, 3 CTAs/SM ----------------------
// smem: A [0, 25600) 64 rows x 400B; W [25600, 64000) 96 rows x 400B;
//       params [64000, 65920)
#define STRIDE_B 400
#define SM_A   0
#define SM_W   25600
#define SM_P   64000
#define SM_TOTAL 65920
#define CSTG_STRIDE 100

__global__ void __launch_bounds__(128, 3)
fused_mlp_kernel(const float* __restrict__ pb,
                 const float* __restrict__ n2g, const float* __restrict__ n2b,
                 const float* __restrict__ b1,  const float* __restrict__ b2,
                 float* __restrict__ outp)
{
    extern __shared__ char smem[];
    const uint32_t sbase = smem_u32(smem);
    const int tid  = threadIdx.x;
    const int wid  = tid >> 5, lane = tid & 31;
    const long rowbase = (long)blockIdx.x * 64;

    float* P = (float*)(smem + SM_P);
    if (tid < 96) {
        P[tid] = pb[tid];  P[96 + tid] = n2g[tid]; P[192 + tid] = n2b[tid];
        P[288 + tid] = b1[tid]; P[384 + tid] = b2[tid];
    }

    // load A (64 x 192 bf16) + W0 (96 x 192 bf16)
    {
        const uint4* Ag = (const uint4*)(g_ext + rowbase * KEXT);
        for (int n = tid; n < 1536; n += 128) {
            const int r = n / 24, m = n - r * 24;
            *(uint4*)(smem + SM_A + r * STRIDE_B + m * 16) = Ag[n];
        }
        const uint4* Wg = (const uint4*)(&g_Wext[0][0]);
        for (int n = tid; n < 2304; n += 128) {
            const int r = n / 24, m = n - r * 24;
            *(uint4*)(smem + SM_W + r * STRIDE_B + m * 16) = Wg[n];
        }
    }
    __syncthreads();

    const int m0  = wid * 16;
    const int g   = lane >> 2;
    const int tig = lane & 3;
    const uint32_t aBase = sbase + SM_A + (uint32_t)(m0 + (lane & 15)) * STRIDE_B
                         + (uint32_t)(lane >> 4) * 16;
    const int jj = lane >> 3;
    const uint32_t bBase = sbase + SM_W
                         + (uint32_t)(((jj >> 1) * 8) + (lane & 7)) * STRIDE_B
                         + (uint32_t)(jj & 1) * 16;

    float accf[12][4];
    float Xf[12][4];

    // byte offsets realizing [Ah|Al|Ah] x [Wh|Wh|Wl] on compact [hi|lo] tiles
#define MAINLOOP()                                                        \
    {                                                                     \
        const int aoff[18] = {0,32,64,96,128,160, 192,224,256,288,320,352,\
                              0,32,64,96,128,160};                        \
        const int boff[18] = {0,32,64,96,128,160, 0,32,64,96,128,160,     \
                              192,224,256,288,320,352};                   \
        _Pragma("unroll")                                                 \
        for (int t = 0; t < 12; t++)                                      \
            { accf[t][0]=0.f; accf[t][1]=0.f; accf[t][2]=0.f; accf[t][3]=0.f; } \
        _Pragma("unroll")                                                 \
        for (int ks = 0; ks < NSTEP; ks++) {                              \
            const uint4 a = ldmat4(aBase + aoff[ks]);                     \
            _Pragma("unroll")                                             \
            for (int nt = 0; nt < 6; nt++) {                              \
                const uint4 bf = ldmat4(bBase + nt * (16 * STRIDE_B) + boff[ks]); \
                mma_bf16(accf[2 * nt    ], a, bf.x, bf.y);                \
                mma_bf16(accf[2 * nt + 1], a, bf.z, bf.w);                \
            }                                                             \
        }                                                                 \
    }

#define WRITE_EXT(vals)                                                   \
    {                                                                     \
        char* rp0 = smem + SM_A + (m0 + g    ) * STRIDE_B;                \
        char* rp1 = smem + SM_A + (m0 + g + 8) * STRIDE_B;                \
        _Pragma("unroll")                                                 \
        for (int t = 0; t < 12; t++) {                                    \
            const int cb = (t * 8 + tig * 2) * 2;                         \
            *(unsigned*)(rp0 + cb)       = bfpack(vals[t][0], vals[t][1], 0); \
            *(unsigned*)(rp0 + 192 + cb) = bfpack(vals[t][0], vals[t][1], 1); \
            *(unsigned*)(rp1 + cb)       = bfpack(vals[t][2], vals[t][3], 0); \
            *(unsigned*)(rp1 + 192 + cb) = bfpack(vals[t][2], vals[t][3], 1); \
        }                                                                 \
    }

#define LOAD_W(idx)                                                      \
    {                                                                     \
        const uint4* Wg = (const uint4*)(&g_Wext[idx][0]);                \
        for (int n = tid; n < 2304; n += 128) {                           \
            const int r = n / 24, m = n - r * 24;                         \
            *(uint4*)(smem + SM_W + r * STRIDE_B + m * 16) = Wg[n];       \
        }                                                                 \
    }

    // ---------------- stage 1: proj + LN2 ----------------------------------
    MAINLOOP();
    __syncthreads();
    LOAD_W(1);                           // prefetch W1 (overlaps epilogue)
    {
        float s1a=0.f, s2a=0.f, s1b=0.f, s2b=0.f;
#pragma unroll
        for (int t = 0; t < 12; t++) {
            const int c0 = t * 8 + tig * 2;
            const float bb0 = P[c0], bb1 = P[c0 + 1];
            Xf[t][0] = accf[t][0] + bb0; Xf[t][1] = accf[t][1] + bb1;
            Xf[t][2] = accf[t][2] + bb0; Xf[t][3] = accf[t][3] + bb1;
            s1a += Xf[t][0] + Xf[t][1];
            s2a += Xf[t][0]*Xf[t][0] + Xf[t][1]*Xf[t][1];
            s1b += Xf[t][2] + Xf[t][3];
            s2b += Xf[t][2]*Xf[t][2] + Xf[t][3]*Xf[t][3];
        }
#pragma unroll
        for (int msk = 1; msk <= 2; msk <<= 1) {
            s1a += __shfl_xor_sync(0xFFFFFFFF, s1a, msk);
            s2a += __shfl_xor_sync(0xFFFFFFFF, s2a, msk);
            s1b += __shfl_xor_sync(0xFFFFFFFF, s1b, msk);
            s2b += __shfl_xor_sync(0xFFFFFFFF, s2b, msk);
        }
        const float mua = s1a * (1.0f/96.0f), mub = s1b * (1.0f/96.0f);
        const float rsa = rsqrtf(s2a * (1.0f/96.0f) - mua*mua + 1e-5f);
        const float rsb = rsqrtf(s2b * (1.0f/96.0f) - mub*mub + 1e-5f);
        float nrm[12][4];
#pragma unroll
        for (int t = 0; t < 12; t++) {
            const int c0 = t * 8 + tig * 2;
            const float g0 = P[96 + c0], g1 = P[96 + c0 + 1];
            const float e0 = P[192 + c0], e1 = P[192 + c0 + 1];
            nrm[t][0] = (Xf[t][0] - mua) * rsa * g0 + e0;
            nrm[t][1] = (Xf[t][1] - mua) * rsa * g1 + e1;
            nrm[t][2] = (Xf[t][2] - mub) * rsb * g0 + e0;
            nrm[t][3] = (Xf[t][3] - mub) * rsb * g1 + e1;
        }
        WRITE_EXT(nrm);
    }
    __syncthreads();

    // ---------------- stage 2: fc1 + GELU -----------------------------------
    MAINLOOP();
    __syncthreads();
    LOAD_W(2);                           // prefetch W2
    {
        float hv[12][4];
#pragma unroll
        for (int t = 0; t < 12; t++) {
            const int c0 = t * 8 + tig * 2;
            const float bb0 = P[288 + c0], bb1 = P[288 + c0 + 1];
            float v0 = accf[t][0] + bb0, v1 = accf[t][1] + bb1;
            float v2 = accf[t][2] + bb0, v3 = accf[t][3] + bb1;
            hv[t][0] = 0.5f * v0 * (1.0f + erff(v0 * 0.70710678118654752440f));
            hv[t][1] = 0.5f * v1 * (1.0f + erff(v1 * 0.70710678118654752440f));
            hv[t][2] = 0.5f * v2 * (1.0f + erff(v2 * 0.70710678118654752440f));
            hv[t][3] = 0.5f * v3 * (1.0f + erff(v3 * 0.70710678118654752440f));
        }
        WRITE_EXT(hv);
    }
    __syncthreads();

    // ---------------- stage 3: fc2 + residual --------------------------------
    MAINLOOP();
    __syncthreads();
    {
        float* Cstg = (float*)(smem + SM_W);
#pragma unroll
        for (int t = 0; t < 12; t++) {
            const int c0 = t * 8 + tig * 2;
            const float bb0 = P[384 + c0], bb1 = P[384 + c0 + 1];
            *(float2*)(Cstg + (m0 + g    ) * CSTG_STRIDE + c0)
                = make_float2(accf[t][0] + bb0 + Xf[t][0], accf[t][1] + bb1 + Xf[t][1]);
            *(float2*)(Cstg + (m0 + g + 8) * CSTG_STRIDE + c0)
                = make_float2(accf[t][2] + bb0 + Xf[t][2], accf[t][3] + bb1 + Xf[t][3]);
        }
        __syncthreads();
        for (int n = tid; n < 1536; n += 128) {
            const int r = n / 24, c4 = n - r * 24;
            const long rw = rowbase + r;
            const int w = (int)(rw >> 6), p = (int)(rw & 63);
            const int b = w >> 10, wy = (w >> 5) & 31, wx = w & 31;
            const int ys = (wy * 8 + (p >> 3) + 4) & 255;
            const int xs = (wx * 8 + (p & 7) + 4) & 255;
            *(float4*)(outp + (size_t)((b * 256 + ys) * 256 + xs) * 96 + c4 * 4)
                = *(float4*)(Cstg + r * CSTG_STRIDE + c4 * 4);
        }
    }
}

// ---------------------------------------------------------------------------
extern "C" void kernel_launch(void* const* d_in, const int* in_sizes, int n_in,
                              void* d_out, int out_size)
{
    const float* q   = (const float*)d_in[0];
    const float* k   = (const float*)d_in[1];
    const float* v   = (const float*)d_in[2];
    const float* rpb = (const float*)d_in[3];
    const float* ng  = (const float*)d_in[4];
    const float* nb  = (const float*)d_in[5];
    const float* pw  = (const float*)d_in[6];
    const float* pb  = (const float*)d_in[7];
    const float* n2g = (const float*)d_in[8];
    const float* n2b = (const float*)d_in[9];
    const float* w1  = (const float*)d_in[10];
    const float* b1  = (const float*)d_in[11];
    const float* w2  = (const float*)d_in[12];
    const float* b2  = (const float*)d_in[13];
    float* out = (float*)d_out;

    cudaFuncSetAttribute(attn_kernel,
                         cudaFuncAttributeMaxDynamicSharedMemorySize, A_SMEM_FLOATS * 4);
    cudaFuncSetAttribute(fused_mlp_kernel,
                         cudaFuncAttributeMaxDynamicSharedMemorySize, SM_TOTAL);

    prep_wext<<<96, 96>>>(pw, w1, w2);
    attn_kernel<<<8192, 192, A_SMEM_FLOATS * 4>>>(q, k, v, rpb, ng, nb);
    fused_mlp_kernel<<<8192, 128, SM_TOTAL>>>(pb, n2g, n2b, b1, b2, out);
}

// round 14
// speedup vs baseline: 2.7297x; 1.0428x over previous
#include <cuda_runtime.h>
#include <cuda_bf16.h>
#include <cstdint>
#include <math.h>

// ---------------------------------------------------------------------------
// BlindSpotBlock: B=8 H=256 W=256 C=96, WS=8 SS=4 NH=6 CH=16
// attention: SIMT (2 queries/thread), 55KB smem via out_s overlay -> 3 CTAs/SM.
// proj/LN2/fc1/GELU/fc2/residual: fused HMMA kernel (bf16x3 via aliasing).
// ---------------------------------------------------------------------------

#define NROWS 524288              // B*NW*64 window-linear rows
#define KEXT  192                 // stored: 96(hi) | 96(lo)
#define NSTEP 18                  // logical K = 288 via aliasing

__device__ __nv_bfloat16 g_ext[(size_t)NROWS * KEXT];   // attention output ext rows
__device__ __nv_bfloat16 g_Wext[3][96 * KEXT];          // [Wh|Wl] per matrix

__device__ __forceinline__ uint32_t smem_u32(const void* p){
    uint32_t a;
    asm("{ .reg .u64 t; cvta.to.shared.u64 t, %1; cvt.u32.u64 %0, t; }" : "=r"(a) : "l"(p));
    return a;
}
__device__ __forceinline__ uint4 ldmat4(uint32_t a){
    uint4 r;
    asm volatile("ldmatrix.sync.aligned.m8n8.x4.shared.b16 {%0,%1,%2,%3}, [%4];"
                 : "=r"(r.x), "=r"(r.y), "=r"(r.z), "=r"(r.w) : "r"(a));
    return r;
}
__device__ __forceinline__ void mma_bf16(float* d, const uint4 a, uint32_t b0, uint32_t b1){
    asm volatile("mma.sync.aligned.m16n8k16.row.col.f32.bf16.bf16.f32 "
                 "{%0,%1,%2,%3}, {%4,%5,%6,%7}, {%8,%9}, {%0,%1,%2,%3};"
                 : "+f"(d[0]), "+f"(d[1]), "+f"(d[2]), "+f"(d[3])
                 : "r"(a.x), "r"(a.y), "r"(a.z), "r"(a.w), "r"(b0), "r"(b1));
}
__device__ __forceinline__ unsigned bfpack(float a, float b, int lo){
    __nv_bfloat16 ha = __float2bfloat16(a), hb = __float2bfloat16(b);
    if (lo) {
        ha = __float2bfloat16(a - __bfloat162float(ha));
        hb = __float2bfloat16(b - __bfloat162float(hb));
    }
    return (unsigned)__bfloat16_as_ushort(ha) | ((unsigned)__bfloat16_as_ushort(hb) << 16);
}

// ---------------- prep: build W_ext = [Wh | Wl] ----------------------------
__global__ void prep_wext(const float* __restrict__ pw,
                          const float* __restrict__ w1,
                          const float* __restrict__ w2)
{
    const int c = blockIdx.x, k = threadIdx.x;
    const float* src[3] = {pw, w1, w2};
#pragma unroll
    for (int m = 0; m < 3; m++) {
        const float wv = src[m][c * 96 + k];
        __nv_bfloat16 bh = __float2bfloat16(wv);
        __nv_bfloat16 bl = __float2bfloat16(wv - __bfloat162float(bh));
        g_Wext[m][c * KEXT + k]      = bh;
        g_Wext[m][c * KEXT + 96 + k] = bl;
    }
}

// ---------------- Kernel A: attention + LN1 -> g_ext -----------------------
// 192 threads: thread=(head hh, lane) owns queries lane and lane+32.
// smem: k_s[0,6144) v_s[6144,12288) rpb[12288,13638) base/reg[13640,13768)
// out_s (64x97=6208 floats) OVERLAYS [0,6208) after the j-loop sync.
#define A_SMEM_FLOATS 13768
__global__ void __launch_bounds__(192, 3)
attn_kernel(const float* __restrict__ q_in,
            const float* __restrict__ k_in,
            const float* __restrict__ v_in,
            const float* __restrict__ rpb,
            const float* __restrict__ ng,
            const float* __restrict__ nb)
{
    extern __shared__ float sm[];
    float* k_s    = sm;
    float* v_s    = sm + 6144;
    float* out_s  = sm;              // overlay, used post-sync
    float* rpb_s  = sm + 12288;
    int*   base_s = (int*)(sm + 13640);
    int*   reg_s  = (int*)(sm + 13704);

    const int tid  = threadIdx.x;
    const int w    = blockIdx.x;
    const int b    = w >> 10;
    const int widx = w & 1023;
    const int wy   = widx >> 5;
    const int wx   = widx & 31;

    if (tid < 64) {
        const int py = tid >> 3, px = tid & 7;
        const int ys = (wy * 8 + py + 4) & 255;
        const int xs = (wx * 8 + px + 4) & 255;
        base_s[tid] = ((b * 256 + ys) * 256 + xs) * 96;
        const int row = wy * 8 + py, col = wx * 8 + px;
        const int rr = (row < 248) ? 0 : ((row < 252) ? 1 : 2);
        const int cr = (col < 248) ? 0 : ((col < 252) ? 1 : 2);
        reg_s[tid] = rr * 3 + cr;
    }
    for (int n = tid; n < 1350; n += 192) rpb_s[n] = rpb[n];
    __syncthreads();

    for (int n = tid; n < 1536; n += 192) {
        const int p = n / 24, c4 = n - p * 24;
        const int g = base_s[p] + c4 * 4;
        *(float4*)(k_s + p * 96 + c4 * 4) = *(const float4*)(k_in + g);
        *(float4*)(v_s + p * 96 + c4 * 4) = *(const float4*)(v_in + g);
    }
    __syncthreads();

    const int hh   = tid >> 5;
    const int lane = tid & 31;
    const int co   = hh * 16;
    const int i0   = lane, i1 = lane + 32;
    const int ri0  = reg_s[i0], ri1 = reg_s[i1];
    const int myoff0 = (112 + (i0 >> 3) * 15 + (i0 & 7)) * 6 + hh;
    const int myoff1 = (112 + (i1 >> 3) * 15 + (i1 & 7)) * 6 + hh;

    float qv0[16], qv1[16];
    {
        const float4* qp = (const float4*)(q_in + base_s[i0] + co);
        float4 a = qp[0], bq = qp[1], c = qp[2], d = qp[3];
        qv0[0]=a.x*0.25f; qv0[1]=a.y*0.25f; qv0[2]=a.z*0.25f; qv0[3]=a.w*0.25f;
        qv0[4]=bq.x*0.25f; qv0[5]=bq.y*0.25f; qv0[6]=bq.z*0.25f; qv0[7]=bq.w*0.25f;
        qv0[8]=c.x*0.25f; qv0[9]=c.y*0.25f; qv0[10]=c.z*0.25f; qv0[11]=c.w*0.25f;
        qv0[12]=d.x*0.25f; qv0[13]=d.y*0.25f; qv0[14]=d.z*0.25f; qv0[15]=d.w*0.25f;
    }
    {
        const float4* qp = (const float4*)(q_in + base_s[i1] + co);
        float4 a = qp[0], bq = qp[1], c = qp[2], d = qp[3];
        qv1[0]=a.x*0.25f; qv1[1]=a.y*0.25f; qv1[2]=a.z*0.25f; qv1[3]=a.w*0.25f;
        qv1[4]=bq.x*0.25f; qv1[5]=bq.y*0.25f; qv1[6]=bq.z*0.25f; qv1[7]=bq.w*0.25f;
        qv1[8]=c.x*0.25f; qv1[9]=c.y*0.25f; qv1[10]=c.z*0.25f; qv1[11]=c.w*0.25f;
        qv1[12]=d.x*0.25f; qv1[13]=d.y*0.25f; qv1[14]=d.z*0.25f; qv1[15]=d.w*0.25f;
    }

    float acc0[16], acc1[16];
#pragma unroll
    for (int c = 0; c < 16; c++) { acc0[c] = 0.f; acc1[c] = 0.f; }
    float ssum0 = 0.f, ssum1 = 0.f;

#pragma unroll 4
    for (int j = 0; j < 64; j++) {
        const float4* kp = (const float4*)(k_s + j * 96 + co);
        float4 k0 = kp[0], k1 = kp[1], k2 = kp[2], k3 = kp[3];
        float a0 = fmaf(qv0[0], k0.x, fmaf(qv0[1], k0.y, fmaf(qv0[2], k0.z, qv0[3] * k0.w)));
        float a1 = fmaf(qv0[4], k1.x, fmaf(qv0[5], k1.y, fmaf(qv0[6], k1.z, qv0[7] * k1.w)));
        float a2 = fmaf(qv0[8], k2.x, fmaf(qv0[9], k2.y, fmaf(qv0[10], k2.z, qv0[11] * k2.w)));
        float a3 = fmaf(qv0[12], k3.x, fmaf(qv0[13], k3.y, fmaf(qv0[14], k3.z, qv0[15] * k3.w)));
        float b0 = fmaf(qv1[0], k0.x, fmaf(qv1[1], k0.y, fmaf(qv1[2], k0.z, qv1[3] * k0.w)));
        float b1 = fmaf(qv1[4], k1.x, fmaf(qv1[5], k1.y, fmaf(qv1[6], k1.z, qv1[7] * k1.w)));
        float b2 = fmaf(qv1[8], k2.x, fmaf(qv1[9], k2.y, fmaf(qv1[10], k2.z, qv1[11] * k2.w)));
        float b3 = fmaf(qv1[12], k3.x, fmaf(qv1[13], k3.y, fmaf(qv1[14], k3.z, qv1[15] * k3.w)));
        const int joff = ((j >> 3) * 15 + (j & 7)) * 6;
        float s0 = (a0 + a1) + (a2 + a3) + rpb_s[myoff0 - joff];
        float s1 = (b0 + b1) + (b2 + b3) + rpb_s[myoff1 - joff];
        const int rj = reg_s[j];
        const float p0 = ((j != i0) && (rj == ri0)) ? __expf(s0) : 0.f;
        const float p1 = ((j != i1) && (rj == ri1)) ? __expf(s1) : 0.f;
        ssum0 += p0; ssum1 += p1;
        const float4* vp = (const float4*)(v_s + j * 96 + co);
        float4 v0 = vp[0], v1 = vp[1], v2 = vp[2], v3 = vp[3];
        acc0[0]=fmaf(p0,v0.x,acc0[0]); acc0[1]=fmaf(p0,v0.y,acc0[1]); acc0[2]=fmaf(p0,v0.z,acc0[2]); acc0[3]=fmaf(p0,v0.w,acc0[3]);
        acc0[4]=fmaf(p0,v1.x,acc0[4]); acc0[5]=fmaf(p0,v1.y,acc0[5]); acc0[6]=fmaf(p0,v1.z,acc0[6]); acc0[7]=fmaf(p0,v1.w,acc0[7]);
        acc0[8]=fmaf(p0,v2.x,acc0[8]); acc0[9]=fmaf(p0,v2.y,acc0[9]); acc0[10]=fmaf(p0,v2.z,acc0[10]); acc0[11]=fmaf(p0,v2.w,acc0[11]);
        acc0[12]=fmaf(p0,v3.x,acc0[12]); acc0[13]=fmaf(p0,v3.y,acc0[13]); acc0[14]=fmaf(p0,v3.z,acc0[14]); acc0[15]=fmaf(p0,v3.w,acc0[15]);
        acc1[0]=fmaf(p1,v0.x,acc1[0]); acc1[1]=fmaf(p1,v0.y,acc1[1]); acc1[2]=fmaf(p1,v0.z,acc1[2]); acc1[3]=fmaf(p1,v0.w,acc1[3]);
        acc1[4]=fmaf(p1,v1.x,acc1[4]); acc1[5]=fmaf(p1,v1.y,acc1[5]); acc1[6]=fmaf(p1,v1.z,acc1[6]); acc1[7]=fmaf(p1,v1.w,acc1[7]);
        acc1[8]=fmaf(p1,v2.x,acc1[8]); acc1[9]=fmaf(p1,v2.y,acc1[9]); acc1[10]=fmaf(p1,v2.z,acc1[10]); acc1[11]=fmaf(p1,v2.w,acc1[11]);
        acc1[12]=fmaf(p1,v3.x,acc1[12]); acc1[13]=fmaf(p1,v3.y,acc1[13]); acc1[14]=fmaf(p1,v3.z,acc1[14]); acc1[15]=fmaf(p1,v3.w,acc1[15]);
    }

    // all k_s/v_s reads complete -> out_s may overlay them
    __syncthreads();

    const float inv0 = 1.0f / ssum0, inv1 = 1.0f / ssum1;
#pragma unroll
    for (int c = 0; c < 16; c++) {
        out_s[i0 * 97 + co + c] = fmaf(acc0[c], inv0, qv0[c]);
        out_s[i1 * 97 + co + c] = fmaf(acc1[c], inv1, qv1[c]);
    }
    __syncthreads();

    // LayerNorm1 (threads 0..63, one row each)
    if (tid < 64) {
        float* r = out_s + tid * 97;
        float s1 = 0.f, s2 = 0.f;
#pragma unroll 8
        for (int c = 0; c < 96; c++) { const float x = r[c]; s1 += x; s2 = fmaf(x, x, s2); }
        const float mu = s1 * (1.0f / 96.0f);
        const float var = s2 * (1.0f / 96.0f) - mu * mu;
        const float rs = rsqrtf(var + 1e-5f);
#pragma unroll 8
        for (int c = 0; c < 96; c++)
            r[c] = (r[c] - mu) * rs * ng[c] + nb[c];
    }
    __syncthreads();

    // write compact ext rows (hi | lo), 24 uint4 per row
    uint4* dst = (uint4*)(g_ext + (size_t)w * 64 * KEXT);
    for (int n = tid; n < 1536; n += 192) {
        const int p = n / 24, m = n - p * 24;
        const int blk = (m >= 12) ? 1 : 0;
        const int cb = (m % 12) * 8;
        const float* r = out_s + p * 97 + cb;
        uint4 u;
        u.x = bfpack(r[0], r[1], blk);
        u.y = bfpack(r[2], r[3], blk);
        u.z = bfpack(r[4], r[5], blk);
        u.w = bfpack(r[6], r[7], blk);
        dst[n] = u;
    }
}

// ---------------- fused MLP: compact tiles, 3 CTAs/SM ----------------------
#define STRIDE_B 400
#define SM_A   0
#define SM_W   25600
#define SM_P   64000
#define SM_TOTAL 65920
#define CSTG_STRIDE 100

__global__ void __launch_bounds__(128, 3)
fused_mlp_kernel(const float* __restrict__ pb,
                 const float* __restrict__ n2g, const float* __restrict__ n2b,
                 const float* __restrict__ b1,  const float* __restrict__ b2,
                 float* __restrict__ outp)
{
    extern __shared__ char smem[];
    const uint32_t sbase = smem_u32(smem);
    const int tid  = threadIdx.x;
    const int wid  = tid >> 5, lane = tid & 31;
    const long rowbase = (long)blockIdx.x * 64;

    float* P = (float*)(smem + SM_P);
    if (tid < 96) {
        P[tid] = pb[tid];  P[96 + tid] = n2g[tid]; P[192 + tid] = n2b[tid];
        P[288 + tid] = b1[tid]; P[384 + tid] = b2[tid];
    }

    {
        const uint4* Ag = (const uint4*)(g_ext + rowbase * KEXT);
        for (int n = tid; n < 1536; n += 128) {
            const int r = n / 24, m = n - r * 24;
            *(uint4*)(smem + SM_A + r * STRIDE_B + m * 16) = Ag[n];
        }
        const uint4* Wg = (const uint4*)(&g_Wext[0][0]);
        for (int n = tid; n < 2304; n += 128) {
            const int r = n / 24, m = n - r * 24;
            *(uint4*)(smem + SM_W + r * STRIDE_B + m * 16) = Wg[n];
        }
    }
    __syncthreads();

    const int m0  = wid * 16;
    const int g   = lane >> 2;
    const int tig = lane & 3;
    const uint32_t aBase = sbase + SM_A + (uint32_t)(m0 + (lane & 15)) * STRIDE_B
                         + (uint32_t)(lane >> 4) * 16;
    const int jj = lane >> 3;
    const uint32_t bBase = sbase + SM_W
                         + (uint32_t)(((jj >> 1) * 8) + (lane & 7)) * STRIDE_B
                         + (uint32_t)(jj & 1) * 16;

    float accf[12][4];
    float Xf[12][4];

#define MAINLOOP()                                                        \
    {                                                                     \
        const int aoff[18] = {0,32,64,96,128,160, 192,224,256,288,320,352,\
                              0,32,64,96,128,160};                        \
        const int boff[18] = {0,32,64,96,128,160, 0,32,64,96,128,160,     \
                              192,224,256,288,320,352};                   \
        _Pragma("unroll")                                                 \
        for (int t = 0; t < 12; t++)                                      \
            { accf[t][0]=0.f; accf[t][1]=0.f; accf[t][2]=0.f; accf[t][3]=0.f; } \
        _Pragma("unroll")                                                 \
        for (int ks = 0; ks < NSTEP; ks++) {                              \
            const uint4 a = ldmat4(aBase + aoff[ks]);                     \
            _Pragma("unroll")                                             \
            for (int nt = 0; nt < 6; nt++) {                              \
                const uint4 bf = ldmat4(bBase + nt * (16 * STRIDE_B) + boff[ks]); \
                mma_bf16(accf[2 * nt    ], a, bf.x, bf.y);                \
                mma_bf16(accf[2 * nt + 1], a, bf.z, bf.w);                \
            }                                                             \
        }                                                                 \
    }

#define WRITE_EXT(vals)                                                   \
    {                                                                     \
        char* rp0 = smem + SM_A + (m0 + g    ) * STRIDE_B;                \
        char* rp1 = smem + SM_A + (m0 + g + 8) * STRIDE_B;                \
        _Pragma("unroll")                                                 \
        for (int t = 0; t < 12; t++) {                                    \
            const int cb = (t * 8 + tig * 2) * 2;                         \
            *(unsigned*)(rp0 + cb)       = bfpack(vals[t][0], vals[t][1], 0); \
            *(unsigned*)(rp0 + 192 + cb) = bfpack(vals[t][0], vals[t][1], 1); \
            *(unsigned*)(rp1 + cb)       = bfpack(vals[t][2], vals[t][3], 0); \
            *(unsigned*)(rp1 + 192 + cb) = bfpack(vals[t][2], vals[t][3], 1); \
        }                                                                 \
    }

#define LOAD_W(idx)                                                      \
    {                                                                     \
        const uint4* Wg = (const uint4*)(&g_Wext[idx][0]);                \
        for (int n = tid; n < 2304; n += 128) {                           \
            const int r = n / 24, m = n - r * 24;                         \
            *(uint4*)(smem + SM_W + r * STRIDE_B + m * 16) = Wg[n];       \
        }                                                                 \
    }

    // ---------------- stage 1: proj + LN2 ----------------------------------
    MAINLOOP();
    __syncthreads();
    LOAD_W(1);
    {
        float s1a=0.f, s2a=0.f, s1b=0.f, s2b=0.f;
#pragma unroll
        for (int t = 0; t < 12; t++) {
            const int c0 = t * 8 + tig * 2;
            const float bb0 = P[c0], bb1 = P[c0 + 1];
            Xf[t][0] = accf[t][0] + bb0; Xf[t][1] = accf[t][1] + bb1;
            Xf[t][2] = accf[t][2] + bb0; Xf[t][3] = accf[t][3] + bb1;
            s1a += Xf[t][0] + Xf[t][1];
            s2a += Xf[t][0]*Xf[t][0] + Xf[t][1]*Xf[t][1];
            s1b += Xf[t][2] + Xf[t][3];
            s2b += Xf[t][2]*Xf[t][2] + Xf[t][3]*Xf[t][3];
        }
#pragma unroll
        for (int msk = 1; msk <= 2; msk <<= 1) {
            s1a += __shfl_xor_sync(0xFFFFFFFF, s1a, msk);
            s2a += __shfl_xor_sync(0xFFFFFFFF, s2a, msk);
            s1b += __shfl_xor_sync(0xFFFFFFFF, s1b, msk);
            s2b += __shfl_xor_sync(0xFFFFFFFF, s2b, msk);
        }
        const float mua = s1a * (1.0f/96.0f), mub = s1b * (1.0f/96.0f);
        const float rsa = rsqrtf(s2a * (1.0f/96.0f) - mua*mua + 1e-5f);
        const float rsb = rsqrtf(s2b * (1.0f/96.0f) - mub*mub + 1e-5f);
        float nrm[12][4];
#pragma unroll
        for (int t = 0; t < 12; t++) {
            const int c0 = t * 8 + tig * 2;
            const float g0 = P[96 + c0], g1 = P[96 + c0 + 1];
            const float e0 = P[192 + c0], e1 = P[192 + c0 + 1];
            nrm[t][0] = (Xf[t][0] - mua) * rsa * g0 + e0;
            nrm[t][1] = (Xf[t][1] - mua) * rsa * g1 + e1;
            nrm[t][2] = (Xf[t][2] - mub) * rsb * g0 + e0;
            nrm[t][3] = (Xf[t][3] - mub) * rsb * g1 + e1;
        }
        WRITE_EXT(nrm);
    }
    __syncthreads();

    // ---------------- stage 2: fc1 + GELU -----------------------------------
    MAINLOOP();
    __syncthreads();
    LOAD_W(2);
    {
        float hv[12][4];
#pragma unroll
        for (int t = 0; t < 12; t++) {
            const int c0 = t * 8 + tig * 2;
            const float bb0 = P[288 + c0], bb1 = P[288 + c0 + 1];
            float v0 = accf[t][0] + bb0, v1 = accf[t][1] + bb1;
            float v2 = accf[t][2] + bb0, v3 = accf[t][3] + bb1;
            hv[t][0] = 0.5f * v0 * (1.0f + erff(v0 * 0.70710678118654752440f));
            hv[t][1] = 0.5f * v1 * (1.0f + erff(v1 * 0.70710678118654752440f));
            hv[t][2] = 0.5f * v2 * (1.0f + erff(v2 * 0.70710678118654752440f));
            hv[t][3] = 0.5f * v3 * (1.0f + erff(v3 * 0.70710678118654752440f));
        }
        WRITE_EXT(hv);
    }
    __syncthreads();

    // ---------------- stage 3: fc2 + residual --------------------------------
    MAINLOOP();
    __syncthreads();
    {
        float* Cstg = (float*)(smem + SM_W);
#pragma unroll
        for (int t = 0; t < 12; t++) {
            const int c0 = t * 8 + tig * 2;
            const float bb0 = P[384 + c0], bb1 = P[384 + c0 + 1];
            *(float2*)(Cstg + (m0 + g    ) * CSTG_STRIDE + c0)
                = make_float2(accf[t][0] + bb0 + Xf[t][0], accf[t][1] + bb1 + Xf[t][1]);
            *(float2*)(Cstg + (m0 + g + 8) * CSTG_STRIDE + c0)
                = make_float2(accf[t][2] + bb0 + Xf[t][2], accf[t][3] + bb1 + Xf[t][3]);
        }
        __syncthreads();
        for (int n = tid; n < 1536; n += 128) {
            const int r = n / 24, c4 = n - r * 24;
            const long rw = rowbase + r;
            const int w = (int)(rw >> 6), p = (int)(rw & 63);
            const int b = w >> 10, wy = (w >> 5) & 31, wx = w & 31;
            const int ys = (wy * 8 + (p >> 3) + 4) & 255;
            const int xs = (wx * 8 + (p & 7) + 4) & 255;
            *(float4*)(outp + (size_t)((b * 256 + ys) * 256 + xs) * 96 + c4 * 4)
                = *(float4*)(Cstg + r * CSTG_STRIDE + c4 * 4);
        }
    }
}

// ---------------------------------------------------------------------------
extern "C" void kernel_launch(void* const* d_in, const int* in_sizes, int n_in,
                              void* d_out, int out_size)
{
    const float* q   = (const float*)d_in[0];
    const float* k   = (const float*)d_in[1];
    const float* v   = (const float*)d_in[2];
    const float* rpb = (const float*)d_in[3];
    const float* ng  = (const float*)d_in[4];
    const float* nb  = (const float*)d_in[5];
    const float* pw  = (const float*)d_in[6];
    const float* pb  = (const float*)d_in[7];
    const float* n2g = (const float*)d_in[8];
    const float* n2b = (const float*)d_in[9];
    const float* w1  = (const float*)d_in[10];
    const float* b1  = (const float*)d_in[11];
    const float* w2  = (const float*)d_in[12];
    const float* b2  = (const float*)d_in[13];
    float* out = (float*)d_out;

    cudaFuncSetAttribute(attn_kernel,
                         cudaFuncAttributeMaxDynamicSharedMemorySize, A_SMEM_FLOATS * 4);
    cudaFuncSetAttribute(fused_mlp_kernel,
                         cudaFuncAttributeMaxDynamicSharedMemorySize, SM_TOTAL);

    prep_wext<<<96, 96>>>(pw, w1, w2);
    attn_kernel<<<8192, 192, A_SMEM_FLOATS * 4>>>(q, k, v, rpb, ng, nb);
    fused_mlp_kernel<<<8192, 128, SM_TOTAL>>>(pb, n2g, n2b, b1, b2, out);
}

// round 15
// speedup vs baseline: 2.9603x; 1.0845x over previous
#include <cuda_runtime.h>
#include <cuda_bf16.h>
#include <cstdint>
#include <math.h>

// ---------------------------------------------------------------------------
// BlindSpotBlock: B=8 H=256 W=256 C=96, WS=8 SS=4 NH=6 CH=16
// attention: HMMA (m16n8k16 bf16 split) per-window kernel -> compact ext rows.
// proj/LN2/fc1/GELU/fc2/residual: fused HMMA kernel (bf16x3 via aliasing).
// ---------------------------------------------------------------------------

#define NROWS 524288              // B*NW*64 window-linear rows
#define KEXT  192                 // stored: 96(hi) | 96(lo)
#define NSTEP 18                  // logical K = 288 via aliasing

__device__ __nv_bfloat16 g_ext[(size_t)NROWS * KEXT];   // attention output ext rows
__device__ __nv_bfloat16 g_Wext[3][96 * KEXT];          // [Wh|Wl] per matrix

__device__ __forceinline__ uint32_t smem_u32(const void* p){
    uint32_t a;
    asm("{ .reg .u64 t; cvta.to.shared.u64 t, %1; cvt.u32.u64 %0, t; }" : "=r"(a) : "l"(p));
    return a;
}
__device__ __forceinline__ uint4 ldmat4(uint32_t a){
    uint4 r;
    asm volatile("ldmatrix.sync.aligned.m8n8.x4.shared.b16 {%0,%1,%2,%3}, [%4];"
                 : "=r"(r.x), "=r"(r.y), "=r"(r.z), "=r"(r.w) : "r"(a));
    return r;
}
__device__ __forceinline__ void mma_bf16(float* d, const uint4 a, uint32_t b0, uint32_t b1){
    asm volatile("mma.sync.aligned.m16n8k16.row.col.f32.bf16.bf16.f32 "
                 "{%0,%1,%2,%3}, {%4,%5,%6,%7}, {%8,%9}, {%0,%1,%2,%3};"
                 : "+f"(d[0]), "+f"(d[1]), "+f"(d[2]), "+f"(d[3])
                 : "r"(a.x), "r"(a.y), "r"(a.z), "r"(a.w), "r"(b0), "r"(b1));
}
__device__ __forceinline__ unsigned bfpack(float a, float b, int lo){
    __nv_bfloat16 ha = __float2bfloat16(a), hb = __float2bfloat16(b);
    if (lo) {
        ha = __float2bfloat16(a - __bfloat162float(ha));
        hb = __float2bfloat16(b - __bfloat162float(hb));
    }
    return (unsigned)__bfloat16_as_ushort(ha) | ((unsigned)__bfloat16_as_ushort(hb) << 16);
}

// ---------------- prep: build W_ext = [Wh | Wl] ----------------------------
__global__ void prep_wext(const float* __restrict__ pw,
                          const float* __restrict__ w1,
                          const float* __restrict__ w2)
{
    const int c = blockIdx.x, k = threadIdx.x;
    const float* src[3] = {pw, w1, w2};
#pragma unroll
    for (int m = 0; m < 3; m++) {
        const float wv = src[m][c * 96 + k];
        __nv_bfloat16 bh = __float2bfloat16(wv);
        __nv_bfloat16 bl = __float2bfloat16(wv - __bfloat162float(bh));
        g_Wext[m][c * KEXT + k]      = bh;
        g_Wext[m][c * KEXT + 96 + k] = bl;
    }
}

// ---------------- Kernel A: HMMA attention + LN1 -> g_ext ------------------
// 256 threads, 8 warps. warp w: rows (w&3)*16, heads (w>>2)*3 .. +2.
// smem bytes:
//   rpb_s  [0, 5408)        1350 floats
//   base_s [5408, 5664)     64 int
//   reg_s  [5664, 5920)     64 int
//   Q_ext  [5920,  31520)   64 rows x 400B   per head h: [qh16|ql16] at h*64
//   K_ext  [31520, 57120)   64 rows x 400B   per head h: [kh16|kl16] at h*64
//   Vt_ext [57120, 83232)   96 rows x 272B   row=h*16+ch: [vh seq64|vl seq64]
//   out_s  [83232, 108064)  64 x 97 floats
#define ASM_RPB  0
#define ASM_BASE 5408
#define ASM_REG  5664
#define ASM_Q    5920
#define ASM_K    31520
#define ASM_V    57120
#define ASM_O    83232
#define ASM_TOTAL 108064
#define QSTR 400
#define VSTR 272

__global__ void __launch_bounds__(256, 2)
attn_kernel(const float* __restrict__ q_in,
            const float* __restrict__ k_in,
            const float* __restrict__ v_in,
            const float* __restrict__ rpb,
            const float* __restrict__ ng,
            const float* __restrict__ nb)
{
    extern __shared__ char smA[];
    const uint32_t sbase = smem_u32(smA);
    float* rpb_s  = (float*)(smA + ASM_RPB);
    int*   base_s = (int*)(smA + ASM_BASE);
    int*   reg_s  = (int*)(smA + ASM_REG);
    float* out_s  = (float*)(smA + ASM_O);

    const int tid  = threadIdx.x;
    const int w    = blockIdx.x;
    const int b    = w >> 10;
    const int widx = w & 1023;
    const int wy   = widx >> 5;
    const int wx   = widx & 31;

    if (tid < 64) {
        const int py = tid >> 3, px = tid & 7;
        const int ys = (wy * 8 + py + 4) & 255;
        const int xs = (wx * 8 + px + 4) & 255;
        base_s[tid] = ((b * 256 + ys) * 256 + xs) * 96;
        const int row = wy * 8 + py, col = wx * 8 + px;
        const int rr = (row < 248) ? 0 : ((row < 252) ? 1 : 2);
        const int cr = (col < 248) ? 0 : ((col < 252) ? 1 : 2);
        reg_s[tid] = rr * 3 + cr;
    }
    for (int n = tid; n < 1350; n += 256) rpb_s[n] = rpb[n];
    __syncthreads();

    // ---- gather + split-convert Q, K, V ------------------------------------
    for (int n = tid; n < 1536; n += 256) {
        const int p = n / 24, c4 = n - p * 24;
        const int hh = c4 >> 2, ch0 = (c4 & 3) * 4;   // 4 channels, same head
        const int g = base_s[p] + c4 * 4;
        // Q (scaled)
        {
            const float4 v = *(const float4*)(q_in + g);
            const float x0 = v.x*0.25f, x1 = v.y*0.25f, x2 = v.z*0.25f, x3 = v.w*0.25f;
            char* rp = smA + ASM_Q + p * QSTR + hh * 64 + ch0 * 2;
            *(unsigned*)(rp)      = bfpack(x0, x1, 0);
            *(unsigned*)(rp + 4)  = bfpack(x2, x3, 0);
            *(unsigned*)(rp + 32) = bfpack(x0, x1, 1);
            *(unsigned*)(rp + 36) = bfpack(x2, x3, 1);
        }
        // K
        {
            const float4 v = *(const float4*)(k_in + g);
            char* rp = smA + ASM_K + p * QSTR + hh * 64 + ch0 * 2;
            *(unsigned*)(rp)      = bfpack(v.x, v.y, 0);
            *(unsigned*)(rp + 4)  = bfpack(v.z, v.w, 0);
            *(unsigned*)(rp + 32) = bfpack(v.x, v.y, 1);
            *(unsigned*)(rp + 36) = bfpack(v.z, v.w, 1);
        }
        // V transposed
        {
            const float4 v = *(const float4*)(v_in + g);
            float xs[4] = {v.x, v.y, v.z, v.w};
#pragma unroll
            for (int e = 0; e < 4; e++) {
                char* rp = smA + ASM_V + (hh * 16 + ch0 + e) * VSTR + p * 2;
                __nv_bfloat16 bh = __float2bfloat16(xs[e]);
                __nv_bfloat16 bl = __float2bfloat16(xs[e] - __bfloat162float(bh));
                *(__nv_bfloat16*)(rp)       = bh;
                *(__nv_bfloat16*)(rp + 128) = bl;
            }
        }
    }
    __syncthreads();

    // ---- per-warp attention -------------------------------------------------
    const int wid  = tid >> 5, lane = tid & 31;
    const int m0   = (wid & 3) * 16;
    const int h0   = (wid >> 2) * 3;
    const int g    = lane >> 2;        // row in group
    const int tig  = lane & 3;
    const int jj   = lane >> 3;

    const int i0r = m0 + g, i1r = i0r + 8;
    const int ri0 = reg_s[i0r], ri1 = reg_s[i1r];
    const int my0 = (112 + (i0r >> 3) * 15 + (i0r & 7)) * 6;   // +hh later
    const int my1 = (112 + (i1r >> 3) * 15 + (i1r & 7)) * 6;

    const uint32_t aQ0 = sbase + ASM_Q + (uint32_t)(m0 + (lane & 15)) * QSTR
                       + (uint32_t)(lane >> 4) * 16;
    const uint32_t bK0 = sbase + ASM_K + (uint32_t)(((jj >> 1) * 8) + (lane & 7)) * QSTR
                       + (uint32_t)(jj & 1) * 16;
    const uint32_t bV0 = sbase + ASM_V + (uint32_t)(((jj >> 1) * 8) + (lane & 7)) * VSTR
                       + (uint32_t)(jj & 1) * 16;

#pragma unroll 1
    for (int hh = h0; hh < h0 + 3; hh++) {
        // ---- QK: S[64 rows x 64 cols] for this warp's 16 rows --------------
        float S[8][4];
#pragma unroll
        for (int t = 0; t < 8; t++) { S[t][0]=0.f; S[t][1]=0.f; S[t][2]=0.f; S[t][3]=0.f; }
        const uint32_t aQ = aQ0 + hh * 64;
        const uint32_t bK = bK0 + hh * 64;
#pragma unroll
        for (int ks = 0; ks < 3; ks++) {
            const uint4 a = ldmat4(aQ + (ks == 1 ? 32u : 0u));
            const uint32_t bo = bK + (ks == 2 ? 32u : 0u);
#pragma unroll
            for (int nt4 = 0; nt4 < 4; nt4++) {
                const uint4 bb = ldmat4(bo + nt4 * (16 * QSTR));
                mma_bf16(S[2*nt4    ], a, bb.x, bb.y);
                mma_bf16(S[2*nt4 + 1], a, bb.z, bb.w);
            }
        }

        // ---- softmax (one-pass, masked, unnormalized) ----------------------
        float rs0 = 0.f, rs1 = 0.f;
#pragma unroll
        for (int nt = 0; nt < 8; nt++) {
            const int j0 = nt * 8 + 2 * tig, j1 = j0 + 1;
            const int jo0 = (nt * 15 + 2 * tig) * 6, jo1 = jo0 + 6;
            const int rj0 = reg_s[j0], rj1 = reg_s[j1];
            const float b00 = rpb_s[my0 - jo0 + hh], b01 = rpb_s[my0 - jo1 + hh];
            const float b10 = rpb_s[my1 - jo0 + hh], b11 = rpb_s[my1 - jo1 + hh];
            float p;
            p = (j0 != i0r && rj0 == ri0) ? __expf(S[nt][0] + b00) : 0.f; S[nt][0] = p; rs0 += p;
            p = (j1 != i0r && rj1 == ri0) ? __expf(S[nt][1] + b01) : 0.f; S[nt][1] = p; rs0 += p;
            p = (j0 != i1r && rj0 == ri1) ? __expf(S[nt][2] + b10) : 0.f; S[nt][2] = p; rs1 += p;
            p = (j1 != i1r && rj1 == ri1) ? __expf(S[nt][3] + b11) : 0.f; S[nt][3] = p; rs1 += p;
        }
        rs0 += __shfl_xor_sync(0xFFFFFFFF, rs0, 1);
        rs0 += __shfl_xor_sync(0xFFFFFFFF, rs0, 2);
        rs1 += __shfl_xor_sync(0xFFFFFFFF, rs1, 1);
        rs1 += __shfl_xor_sync(0xFFFFFFFF, rs1, 2);

        // ---- pack P (fp32) -> A fragments hi/lo (C-layout == A-layout) -----
        uint4 ah[4], al[4];
#pragma unroll
        for (int kt = 0; kt < 4; kt++) {
            ah[kt].x = bfpack(S[2*kt  ][0], S[2*kt  ][1], 0);
            ah[kt].y = bfpack(S[2*kt  ][2], S[2*kt  ][3], 0);
            ah[kt].z = bfpack(S[2*kt+1][0], S[2*kt+1][1], 0);
            ah[kt].w = bfpack(S[2*kt+1][2], S[2*kt+1][3], 0);
            al[kt].x = bfpack(S[2*kt  ][0], S[2*kt  ][1], 1);
            al[kt].y = bfpack(S[2*kt  ][2], S[2*kt  ][3], 1);
            al[kt].z = bfpack(S[2*kt+1][0], S[2*kt+1][1], 1);
            al[kt].w = bfpack(S[2*kt+1][2], S[2*kt+1][3], 1);
        }

        // ---- AV: O[16 x 16] = Ph@Vh + Pl@Vh + Ph@Vl ------------------------
        const uint32_t bV = bV0 + (uint32_t)(hh * 16) * VSTR;
        uint4 vh[4], vl[4];
#pragma unroll
        for (int ks = 0; ks < 4; ks++) {
            vh[ks] = ldmat4(bV + ks * 32);
            vl[ks] = ldmat4(bV + 128 + ks * 32);
        }
        float O0[4] = {0.f, 0.f, 0.f, 0.f};
        float O1[4] = {0.f, 0.f, 0.f, 0.f};
#pragma unroll
        for (int ks = 0; ks < 4; ks++) {
            mma_bf16(O0, ah[ks], vh[ks].x, vh[ks].y);
            mma_bf16(O1, ah[ks], vh[ks].z, vh[ks].w);
        }
#pragma unroll
        for (int ks = 0; ks < 4; ks++) {
            mma_bf16(O0, al[ks], vh[ks].x, vh[ks].y);
            mma_bf16(O1, al[ks], vh[ks].z, vh[ks].w);
        }
#pragma unroll
        for (int ks = 0; ks < 4; ks++) {
            mma_bf16(O0, ah[ks], vl[ks].x, vl[ks].y);
            mma_bf16(O1, ah[ks], vl[ks].z, vl[ks].w);
        }

        // ---- normalize + fp32 residual (qh+ql) + store rows to out_s -------
        const float inv0 = 1.0f / rs0, inv1 = 1.0f / rs1;
#pragma unroll
        for (int c = 0; c < 4; c++) {
            const int row = (c >> 1) ? i1r : i0r;
            const float inv = (c >> 1) ? inv1 : inv0;
            const int chl0 = 2 * tig + (c & 1);          // nt0: ch 0..7
            // nt = 0 (ch 0-7)
            {
                const char* qp = smA + ASM_Q + row * QSTR + hh * 64 + chl0 * 2;
                const float qs = __bfloat162float(*(const __nv_bfloat16*)(qp))
                               + __bfloat162float(*(const __nv_bfloat16*)(qp + 32));
                out_s[row * 97 + hh * 16 + chl0] = O0[c] * inv + qs;
            }
            // nt = 1 (ch 8-15)
            {
                const int chl1 = chl0 + 8;
                const char* qp = smA + ASM_Q + row * QSTR + hh * 64 + chl1 * 2;
                const float qs = __bfloat162float(*(const __nv_bfloat16*)(qp))
                               + __bfloat162float(*(const __nv_bfloat16*)(qp + 32));
                out_s[row * 97 + hh * 16 + chl1] = O1[c] * inv + qs;
            }
        }
    }
    __syncthreads();

    // ---- LayerNorm1 (threads 0..63, one row each) --------------------------
    if (tid < 64) {
        float* r = out_s + tid * 97;
        float s1 = 0.f, s2 = 0.f;
#pragma unroll 8
        for (int c = 0; c < 96; c++) { const float x = r[c]; s1 += x; s2 = fmaf(x, x, s2); }
        const float mu = s1 * (1.0f / 96.0f);
        const float var = s2 * (1.0f / 96.0f) - mu * mu;
        const float rs = rsqrtf(var + 1e-5f);
#pragma unroll 8
        for (int c = 0; c < 96; c++)
            r[c] = (r[c] - mu) * rs * ng[c] + nb[c];
    }
    __syncthreads();

    // ---- compact ext store (hi | lo), 24 uint4 per row ---------------------
    uint4* dst = (uint4*)(g_ext + (size_t)w * 64 * KEXT);
    for (int n = tid; n < 1536; n += 256) {
        const int p = n / 24, m = n - p * 24;
        const int blk = (m >= 12) ? 1 : 0;
        const int cb = (m % 12) * 8;
        const float* r = out_s + p * 97 + cb;
        uint4 u;
        u.x = bfpack(r[0], r[1], blk);
        u.y = bfpack(r[2], r[3], blk);
        u.z = bfpack(r[4], r[5], blk);
        u.w = bfpack(r[6], r[7], blk);
        dst[n] = u;
    }
}

// ---------------- fused MLP: compact tiles, 3 CTAs/SM ----------------------
#define STRIDE_B 400
#define SM_A   0
#define SM_W   25600
#define SM_P   64000
#define SM_TOTAL 65920
#define CSTG_STRIDE 100

__global__ void __launch_bounds__(128, 3)
fused_mlp_kernel(const float* __restrict__ pb,
                 const float* __restrict__ n2g, const float* __restrict__ n2b,
                 const float* __restrict__ b1,  const float* __restrict__ b2,
                 float* __restrict__ outp)
{
    extern __shared__ char smem[];
    const uint32_t sbase = smem_u32(smem);
    const int tid  = threadIdx.x;
    const int wid  = tid >> 5, lane = tid & 31;
    const long rowbase = (long)blockIdx.x * 64;

    float* P = (float*)(smem + SM_P);
    if (tid < 96) {
        P[tid] = pb[tid];  P[96 + tid] = n2g[tid]; P[192 + tid] = n2b[tid];
        P[288 + tid] = b1[tid]; P[384 + tid] = b2[tid];
    }

    {
        const uint4* Ag = (const uint4*)(g_ext + rowbase * KEXT);
        for (int n = tid; n < 1536; n += 128) {
            const int r = n / 24, m = n - r * 24;
            *(uint4*)(smem + SM_A + r * STRIDE_B + m * 16) = Ag[n];
        }
        const uint4* Wg = (const uint4*)(&g_Wext[0][0]);
        for (int n = tid; n < 2304; n += 128) {
            const int r = n / 24, m = n - r * 24;
            *(uint4*)(smem + SM_W + r * STRIDE_B + m * 16) = Wg[n];
        }
    }
    __syncthreads();

    const int m0  = wid * 16;
    const int g   = lane >> 2;
    const int tig = lane & 3;
    const uint32_t aBase = sbase + SM_A + (uint32_t)(m0 + (lane & 15)) * STRIDE_B
                         + (uint32_t)(lane >> 4) * 16;
    const int jj = lane >> 3;
    const uint32_t bBase = sbase + SM_W
                         + (uint32_t)(((jj >> 1) * 8) + (lane & 7)) * STRIDE_B
                         + (uint32_t)(jj & 1) * 16;

    float accf[12][4];
    float Xf[12][4];

#define MAINLOOP()                                                        \
    {                                                                     \
        const int aoff[18] = {0,32,64,96,128,160, 192,224,256,288,320,352,\
                              0,32,64,96,128,160};                        \
        const int boff[18] = {0,32,64,96,128,160, 0,32,64,96,128,160,     \
                              192,224,256,288,320,352};                   \
        _Pragma("unroll")                                                 \
        for (int t = 0; t < 12; t++)                                      \
            { accf[t][0]=0.f; accf[t][1]=0.f; accf[t][2]=0.f; accf[t][3]=0.f; } \
        _Pragma("unroll")                                                 \
        for (int ks = 0; ks < NSTEP; ks++) {                              \
            const uint4 a = ldmat4(aBase + aoff[ks]);                     \
            _Pragma("unroll")                                             \
            for (int nt = 0; nt < 6; nt++) {                              \
                const uint4 bf = ldmat4(bBase + nt * (16 * STRIDE_B) + boff[ks]); \
                mma_bf16(accf[2 * nt    ], a, bf.x, bf.y);                \
                mma_bf16(accf[2 * nt + 1], a, bf.z, bf.w);                \
            }                                                             \
        }                                                                 \
    }

#define WRITE_EXT(vals)                                                   \
    {                                                                     \
        char* rp0 = smem + SM_A + (m0 + g    ) * STRIDE_B;                \
        char* rp1 = smem + SM_A + (m0 + g + 8) * STRIDE_B;                \
        _Pragma("unroll")                                                 \
        for (int t = 0; t < 12; t++) {                                    \
            const int cb = (t * 8 + tig * 2) * 2;                         \
            *(unsigned*)(rp0 + cb)       = bfpack(vals[t][0], vals[t][1], 0); \
            *(unsigned*)(rp0 + 192 + cb) = bfpack(vals[t][0], vals[t][1], 1); \
            *(unsigned*)(rp1 + cb)       = bfpack(vals[t][2], vals[t][3], 0); \
            *(unsigned*)(rp1 + 192 + cb) = bfpack(vals[t][2], vals[t][3], 1); \
        }                                                                 \
    }

#define LOAD_W(idx)                                                      \
    {                                                                     \
        const uint4* Wg = (const uint4*)(&g_Wext[idx][0]);                \
        for (int n = tid; n < 2304; n += 128) {                           \
            const int r = n / 24, m = n - r * 24;                         \
            *(uint4*)(smem + SM_W + r * STRIDE_B + m * 16) = Wg[n];       \
        }                                                                 \
    }

    // ---------------- stage 1: proj + LN2 ----------------------------------
    MAINLOOP();
    __syncthreads();
    LOAD_W(1);
    {
        float s1a=0.f, s2a=0.f, s1b=0.f, s2b=0.f;
#pragma unroll
        for (int t = 0; t < 12; t++) {
            const int c0 = t * 8 + tig * 2;
            const float bb0 = P[c0], bb1 = P[c0 + 1];
            Xf[t][0] = accf[t][0] + bb0; Xf[t][1] = accf[t][1] + bb1;
            Xf[t][2] = accf[t][2] + bb0; Xf[t][3] = accf[t][3] + bb1;
            s1a += Xf[t][0] + Xf[t][1];
            s2a += Xf[t][0]*Xf[t][0] + Xf[t][1]*Xf[t][1];
            s1b += Xf[t][2] + Xf[t][3];
            s2b += Xf[t][2]*Xf[t][2] + Xf[t][3]*Xf[t][3];
        }
#pragma unroll
        for (int msk = 1; msk <= 2; msk <<= 1) {
            s1a += __shfl_xor_sync(0xFFFFFFFF, s1a, msk);
            s2a += __shfl_xor_sync(0xFFFFFFFF, s2a, msk);
            s1b += __shfl_xor_sync(0xFFFFFFFF, s1b, msk);
            s2b += __shfl_xor_sync(0xFFFFFFFF, s2b, msk);
        }
        const float mua = s1a * (1.0f/96.0f), mub = s1b * (1.0f/96.0f);
        const float rsa = rsqrtf(s2a * (1.0f/96.0f) - mua*mua + 1e-5f);
        const float rsb = rsqrtf(s2b * (1.0f/96.0f) - mub*mub + 1e-5f);
        float nrm[12][4];
#pragma unroll
        for (int t = 0; t < 12; t++) {
            const int c0 = t * 8 + tig * 2;
            const float g0 = P[96 + c0], g1 = P[96 + c0 + 1];
            const float e0 = P[192 + c0], e1 = P[192 + c0 + 1];
            nrm[t][0] = (Xf[t][0] - mua) * rsa * g0 + e0;
            nrm[t][1] = (Xf[t][1] - mua) * rsa * g1 + e1;
            nrm[t][2] = (Xf[t][2] - mub) * rsb * g0 + e0;
            nrm[t][3] = (Xf[t][3] - mub) * rsb * g1 + e1;
        }
        WRITE_EXT(nrm);
    }
    __syncthreads();

    // ---------------- stage 2: fc1 + GELU -----------------------------------
    MAINLOOP();
    __syncthreads();
    LOAD_W(2);
    {
        float hv[12][4];
#pragma unroll
        for (int t = 0; t < 12; t++) {
            const int c0 = t * 8 + tig * 2;
            const float bb0 = P[288 + c0], bb1 = P[288 + c0 + 1];
            float v0 = accf[t][0] + bb0, v1 = accf[t][1] + bb1;
            float v2 = accf[t][2] + bb0, v3 = accf[t][3] + bb1;
            hv[t][0] = 0.5f * v0 * (1.0f + erff(v0 * 0.70710678118654752440f));
            hv[t][1] = 0.5f * v1 * (1.0f + erff(v1 * 0.70710678118654752440f));
            hv[t][2] = 0.5f * v2 * (1.0f + erff(v2 * 0.70710678118654752440f));
            hv[t][3] = 0.5f * v3 * (1.0f + erff(v3 * 0.70710678118654752440f));
        }
        WRITE_EXT(hv);
    }
    __syncthreads();

    // ---------------- stage 3: fc2 + residual --------------------------------
    MAINLOOP();
    __syncthreads();
    {
        float* Cstg = (float*)(smem + SM_W);
#pragma unroll
        for (int t = 0; t < 12; t++) {
            const int c0 = t * 8 + tig * 2;
            const float bb0 = P[384 + c0], bb1 = P[384 + c0 + 1];
            *(float2*)(Cstg + (m0 + g    ) * CSTG_STRIDE + c0)
                = make_float2(accf[t][0] + bb0 + Xf[t][0], accf[t][1] + bb1 + Xf[t][1]);
            *(float2*)(Cstg + (m0 + g + 8) * CSTG_STRIDE + c0)
                = make_float2(accf[t][2] + bb0 + Xf[t][2], accf[t][3] + bb1 + Xf[t][3]);
        }
        __syncthreads();
        for (int n = tid; n < 1536; n += 128) {
            const int r = n / 24, c4 = n - r * 24;
            const long rw = rowbase + r;
            const int w = (int)(rw >> 6), p = (int)(rw & 63);
            const int b = w >> 10, wy = (w >> 5) & 31, wx = w & 31;
            const int ys = (wy * 8 + (p >> 3) + 4) & 255;
            const int xs = (wx * 8 + (p & 7) + 4) & 255;
            *(float4*)(outp + (size_t)((b * 256 + ys) * 256 + xs) * 96 + c4 * 4)
                = *(float4*)(Cstg + r * CSTG_STRIDE + c4 * 4);
        }
    }
}

// ---------------------------------------------------------------------------
extern "C" void kernel_launch(void* const* d_in, const int* in_sizes, int n_in,
                              void* d_out, int out_size)
{
    const float* q   = (const float*)d_in[0];
    const float* k   = (const float*)d_in[1];
    const float* v   = (const float*)d_in[2];
    const float* rpb = (const float*)d_in[3];
    const float* ng  = (const float*)d_in[4];
    const float* nb  = (const float*)d_in[5];
    const float* pw  = (const float*)d_in[6];
    const float* pb  = (const float*)d_in[7];
    const float* n2g = (const float*)d_in[8];
    const float* n2b = (const float*)d_in[9];
    const float* w1  = (const float*)d_in[10];
    const float* b1  = (const float*)d_in[11];
    const float* w2  = (const float*)d_in[12];
    const float* b2  = (const float*)d_in[13];
    float* out = (float*)d_out;

    cudaFuncSetAttribute(attn_kernel,
                         cudaFuncAttributeMaxDynamicSharedMemorySize, ASM_TOTAL);
    cudaFuncSetAttribute(fused_mlp_kernel,
                         cudaFuncAttributeMaxDynamicSharedMemorySize, SM_TOTAL);

    prep_wext<<<96, 96>>>(pw, w1, w2);
    attn_kernel<<<8192, 256, ASM_TOTAL>>>(q, k, v, rpb, ng, nb);
    fused_mlp_kernel<<<8192, 128, SM_TOTAL>>>(pb, n2g, n2b, b1, b2, out);
}